// round 1
// baseline (speedup 1.0000x reference)
#include <cuda_runtime.h>
#include <math.h>
#include <stdint.h>

// GPT-2 small fwd: B=2 T=1024 E=768 H=12 L=6 V=50257
#define NB 2
#define NTOK 1024
#define NE 768
#define NH 12
#define DH 64
#define NL 6
#define NV 50257
#define NM (NB*NTOK)     // 2048 tokens
#define N3 (3*NE)        // 2304
#define N4 (4*NE)        // 3072

// ---------------- scratch (device globals; no allocation allowed) -------------
static __device__ float g_x  [NM*NE];
static __device__ float g_h  [NM*NE];
static __device__ float g_qkv[NM*N3];
static __device__ float g_att[(size_t)NB*NH*NTOK*NTOK];   // ~100.7 MB
static __device__ float g_y  [NM*NE];
static __device__ float g_fc [NM*N4];
static __device__ float g_logits[(size_t)NM*NV];           // fallback if d_out is loss-only
static __device__ float g_rl [NM];

// ---------------- embed: x = wte[x0] + wpe ------------------------------------
__global__ void embed_kernel(const int* __restrict__ x0,
                             const float* __restrict__ wte,
                             const float* __restrict__ wpe,
                             float* __restrict__ x) {
    int i = blockIdx.x * blockDim.x + threadIdx.x;
    if (i >= NM * NE) return;
    int tok = i / NE, e = i - tok * NE;
    int t = tok % NTOK;
    int id = x0[tok];
    x[i] = wte[(size_t)id * NE + e] + wpe[(size_t)t * NE + e];
}

// ---------------- layernorm (biased var, eps=1e-6) -----------------------------
__global__ void __launch_bounds__(256) ln_kernel(const float* __restrict__ x,
                                                 const float* __restrict__ w,
                                                 const float* __restrict__ b,
                                                 float* __restrict__ out) {
    int tok = blockIdx.x;
    const float* row = x + (size_t)tok * NE;
    __shared__ float red[256];
    int tid = threadIdx.x;

    float s = 0.f;
    for (int e = tid; e < NE; e += 256) s += row[e];
    red[tid] = s; __syncthreads();
    for (int o = 128; o > 0; o >>= 1) { if (tid < o) red[tid] += red[tid + o]; __syncthreads(); }
    float mean = red[0] * (1.0f / NE);
    __syncthreads();

    float v = 0.f;
    for (int e = tid; e < NE; e += 256) { float d = row[e] - mean; v += d * d; }
    red[tid] = v; __syncthreads();
    for (int o = 128; o > 0; o >>= 1) { if (tid < o) red[tid] += red[tid + o]; __syncthreads(); }
    float rstd = rsqrtf(red[0] * (1.0f / NE) + 1e-6f);

    for (int e = tid; e < NE; e += 256)
        out[(size_t)tok * NE + e] = (row[e] - mean) * rstd * w[e] + b[e];
}

// ---------------- generic SGEMM: 64x64x16 tile, 256 thr, 4x4 microtile ---------
// EPI: 0 = none, 1 = C = R + A*B (residual), 2 = C = gelu(A*B)
__device__ __forceinline__ float gelu_tanh(float x) {
    const float c = 0.7978845608028654f;  // sqrt(2/pi)
    float x3 = x * x * x;
    return 0.5f * x * (1.0f + tanhf(c * (x + 0.044715f * x3)));
}

template<int EPI, bool TB>
__global__ void __launch_bounds__(256) gemm_kernel(
    const float* __restrict__ A, const float* __restrict__ B,
    float* __restrict__ C, const float* __restrict__ R,
    int M, int N, int K)
{
    __shared__ float As[16][68];
    __shared__ float Bs[16][68];
    const int tid = threadIdx.x;
    const int m0 = blockIdx.y * 64;
    const int n0 = blockIdx.x * 64;
    const int ty = tid >> 4, tx = tid & 15;
    const int lr = tid >> 2;          // 0..63 (row within tile)
    const int lk = (tid & 3) * 4;     // 0,4,8,12 (k quad)
    float acc[4][4] = {};

    for (int k0 = 0; k0 < K; k0 += 16) {
        { // A tile: [64 m][16 k] -> As[k][m]
            float4 v = *(const float4*)(A + (size_t)(m0 + lr) * K + k0 + lk);
            As[lk+0][lr] = v.x; As[lk+1][lr] = v.y;
            As[lk+2][lr] = v.z; As[lk+3][lr] = v.w;
        }
        if (TB) { // B [N,K]: tile [64 n][16 k] -> Bs[k][n]
            int n = n0 + lr;
            float4 v = make_float4(0.f, 0.f, 0.f, 0.f);
            if (n < N) v = *(const float4*)(B + (size_t)n * K + k0 + lk);
            Bs[lk+0][lr] = v.x; Bs[lk+1][lr] = v.y;
            Bs[lk+2][lr] = v.z; Bs[lk+3][lr] = v.w;
        } else {  // B [K,N]: tile [16 k][64 n] -> Bs[k][n]
            int k  = tid >> 4;
            int nq = (tid & 15) * 4;
            int n  = n0 + nq;
            float4 v = make_float4(0.f, 0.f, 0.f, 0.f);
            const float* bp = B + (size_t)(k0 + k) * N;
            if (n + 3 < N) v = *(const float4*)(bp + n);
            else {
                if (n + 0 < N) v.x = bp[n + 0];
                if (n + 1 < N) v.y = bp[n + 1];
                if (n + 2 < N) v.z = bp[n + 2];
            }
            *(float4*)&Bs[k][nq] = v;
        }
        __syncthreads();
#pragma unroll
        for (int k = 0; k < 16; ++k) {
            float4 a = *(const float4*)&As[k][ty * 4];
            float4 b = *(const float4*)&Bs[k][tx * 4];
            float av[4] = {a.x, a.y, a.z, a.w};
            float bv[4] = {b.x, b.y, b.z, b.w};
#pragma unroll
            for (int i = 0; i < 4; ++i)
#pragma unroll
                for (int j = 0; j < 4; ++j)
                    acc[i][j] = fmaf(av[i], bv[j], acc[i][j]);
        }
        __syncthreads();
    }

#pragma unroll
    for (int i = 0; i < 4; ++i) {
        int m = m0 + ty * 4 + i;
#pragma unroll
        for (int j = 0; j < 4; ++j) {
            int n = n0 + tx * 4 + j;
            if (n < N) {
                float v = acc[i][j];
                if (EPI == 1) v += R[(size_t)m * N + n];
                if (EPI == 2) v = gelu_tanh(v);
                C[(size_t)m * N + n] = v;
            }
        }
    }
}

// ---------------- attention: scores S = Q K^T * scale --------------------------
__global__ void __launch_bounds__(256) attn_scores(const float* __restrict__ qkv,
                                                   float* __restrict__ att) {
    if (blockIdx.x > blockIdx.y) return;  // tile fully above diagonal
    int bh = blockIdx.z;
    int b = bh / NH, h = bh % NH;
    int t0 = blockIdx.y * 64, s0 = blockIdx.x * 64;
    __shared__ float Qs[64][68];   // [d][t]
    __shared__ float Ks[64][68];   // [d][s]
    int tid = threadIdx.x;

#pragma unroll
    for (int i = 0; i < 4; ++i) {
        int l = tid + i * 256;      // float4 unit id, 0..1023
        int r = l >> 4;             // row in tile
        int dq = (l & 15) * 4;      // d quad
        float4 q = *(const float4*)(qkv + (size_t)(b * NTOK + t0 + r) * N3 + h * DH + dq);
        Qs[dq+0][r] = q.x; Qs[dq+1][r] = q.y; Qs[dq+2][r] = q.z; Qs[dq+3][r] = q.w;
        float4 k = *(const float4*)(qkv + (size_t)(b * NTOK + s0 + r) * N3 + NE + h * DH + dq);
        Ks[dq+0][r] = k.x; Ks[dq+1][r] = k.y; Ks[dq+2][r] = k.z; Ks[dq+3][r] = k.w;
    }
    __syncthreads();

    int ty = tid >> 4, tx = tid & 15;
    float acc[4][4] = {};
#pragma unroll
    for (int d = 0; d < 64; ++d) {
        float4 a = *(const float4*)&Qs[d][ty * 4];
        float4 b4 = *(const float4*)&Ks[d][tx * 4];
        float av[4] = {a.x, a.y, a.z, a.w};
        float bv[4] = {b4.x, b4.y, b4.z, b4.w};
#pragma unroll
        for (int i = 0; i < 4; ++i)
#pragma unroll
            for (int j = 0; j < 4; ++j)
                acc[i][j] = fmaf(av[i], bv[j], acc[i][j]);
    }
    const float scale = 0.125f;  // 1/sqrt(64)
#pragma unroll
    for (int i = 0; i < 4; ++i) {
        int t = t0 + ty * 4 + i;
#pragma unroll
        for (int j = 0; j < 4; ++j) {
            int s = s0 + tx * 4 + j;
            att[((size_t)bh * NTOK + t) * NTOK + s] = acc[i][j] * scale;
        }
    }
}

// ---------------- causal softmax (row-wise, masked by index) -------------------
__global__ void __launch_bounds__(256) attn_softmax(float* __restrict__ att) {
    int row = blockIdx.x;          // bh*NTOK + t
    int t = row % NTOK;
    float* p = att + (size_t)row * NTOK;
    int n = t + 1;
    __shared__ float red[256];
    int tid = threadIdx.x;

    float m = -INFINITY;
    for (int s = tid; s < n; s += 256) m = fmaxf(m, p[s]);
    red[tid] = m; __syncthreads();
    for (int o = 128; o > 0; o >>= 1) { if (tid < o) red[tid] = fmaxf(red[tid], red[tid + o]); __syncthreads(); }
    m = red[0];
    __syncthreads();

    float s0 = 0.f;
    for (int s = tid; s < n; s += 256) s0 += expf(p[s] - m);
    red[tid] = s0; __syncthreads();
    for (int o = 128; o > 0; o >>= 1) { if (tid < o) red[tid] += red[tid + o]; __syncthreads(); }
    float inv = 1.0f / red[0];

    for (int s = tid; s < NTOK; s += 256)
        p[s] = (s < n) ? expf(p[s] - m) * inv : 0.0f;
}

// ---------------- attention: Y = P V ------------------------------------------
__global__ void __launch_bounds__(256) attn_av(const float* __restrict__ att,
                                               const float* __restrict__ qkv,
                                               float* __restrict__ y) {
    int bh = blockIdx.y;
    int b = bh / NH, h = bh % NH;
    int t0 = blockIdx.x * 64;
    __shared__ float Ps[64][68];   // [s][t]
    __shared__ float Vs[64][68];   // [s][d]
    int tid = threadIdx.x;
    int ty = tid >> 4, tx = tid & 15;
    float acc[4][4] = {};

    for (int c = 0; c <= blockIdx.x; ++c) {
        int s0 = c * 64;
#pragma unroll
        for (int i = 0; i < 4; ++i) {
            int l = tid + i * 256;
            int r = l >> 4;
            int q = (l & 15) * 4;
            float4 pv = *(const float4*)(att + ((size_t)bh * NTOK + t0 + r) * NTOK + s0 + q);
            Ps[q+0][r] = pv.x; Ps[q+1][r] = pv.y; Ps[q+2][r] = pv.z; Ps[q+3][r] = pv.w;
            float4 vv = *(const float4*)(qkv + (size_t)(b * NTOK + s0 + r) * N3 + 2 * NE + h * DH + q);
            *(float4*)&Vs[r][q] = vv;
        }
        __syncthreads();
#pragma unroll
        for (int s = 0; s < 64; ++s) {
            float4 a = *(const float4*)&Ps[s][ty * 4];
            float4 b4 = *(const float4*)&Vs[s][tx * 4];
            float av[4] = {a.x, a.y, a.z, a.w};
            float bv[4] = {b4.x, b4.y, b4.z, b4.w};
#pragma unroll
            for (int i = 0; i < 4; ++i)
#pragma unroll
                for (int j = 0; j < 4; ++j)
                    acc[i][j] = fmaf(av[i], bv[j], acc[i][j]);
        }
        __syncthreads();
    }
#pragma unroll
    for (int i = 0; i < 4; ++i) {
        int t = t0 + ty * 4 + i;
#pragma unroll
        for (int j = 0; j < 4; ++j) {
            int d = tx * 4 + j;
            y[(size_t)(b * NTOK + t) * NE + h * DH + d] = acc[i][j];
        }
    }
}

// ---------------- loss: per-row logsumexp + target gather ----------------------
__global__ void __launch_bounds__(256) loss_rows(const float* __restrict__ logits,
                                                 const int* __restrict__ tgt,
                                                 float* __restrict__ rl) {
    int row = blockIdx.x;
    const float* p = logits + (size_t)row * NV;
    __shared__ float sm[256], ss[256];
    int tid = threadIdx.x;

    float m = -INFINITY, s = 0.f;
    for (int j = tid; j < NV; j += 256) {
        float v = p[j];
        float nm = fmaxf(m, v);
        s = s * expf(m - nm) + expf(v - nm);
        m = nm;
    }
    sm[tid] = m; ss[tid] = s; __syncthreads();
    for (int o = 128; o > 0; o >>= 1) {
        if (tid < o) {
            float m2 = sm[tid + o], s2 = ss[tid + o];
            float M = fmaxf(sm[tid], m2);
            ss[tid] = ss[tid] * expf(sm[tid] - M) + s2 * expf(m2 - M);
            sm[tid] = M;
        }
        __syncthreads();
    }
    if (tid == 0) {
        float lt = p[tgt[row]];
        rl[row] = -(lt - sm[0] - logf(ss[0]));
    }
}

__global__ void __launch_bounds__(256) loss_final(const float* __restrict__ rl,
                                                  float* __restrict__ out) {
    __shared__ float red[256];
    int tid = threadIdx.x;
    float s = 0.f;
    for (int i = tid; i < NM; i += 256) s += rl[i];
    red[tid] = s; __syncthreads();
    for (int o = 128; o > 0; o >>= 1) { if (tid < o) red[tid] += red[tid + o]; __syncthreads(); }
    if (tid == 0) out[0] = red[0] * (1.0f / NM);
}

// ---------------- host orchestration -------------------------------------------
extern "C" void kernel_launch(void* const* d_in, const int* in_sizes, int n_in,
                              void* d_out, int out_size) {
    const int*   x0    = (const int*)  d_in[0];
    const int*   tgt   = (const int*)  d_in[1];
    const float* wte   = (const float*)d_in[2];
    const float* wpe   = (const float*)d_in[3];
    const float* ln1w  = (const float*)d_in[4];
    const float* ln1b  = (const float*)d_in[5];
    const float* Wqkv  = (const float*)d_in[6];
    const float* Wo    = (const float*)d_in[7];
    const float* ln2w  = (const float*)d_in[8];
    const float* ln2b  = (const float*)d_in[9];
    const float* Wfc   = (const float*)d_in[10];
    const float* Wproj = (const float*)d_in[11];
    const float* lnfw  = (const float*)d_in[12];
    const float* lnfb  = (const float*)d_in[13];

    float *px, *ph, *pq, *pa, *py, *pf, *pl, *prl;
    cudaGetSymbolAddress((void**)&px,  g_x);
    cudaGetSymbolAddress((void**)&ph,  g_h);
    cudaGetSymbolAddress((void**)&pq,  g_qkv);
    cudaGetSymbolAddress((void**)&pa,  g_att);
    cudaGetSymbolAddress((void**)&py,  g_y);
    cudaGetSymbolAddress((void**)&pf,  g_fc);
    cudaGetSymbolAddress((void**)&pl,  g_logits);
    cudaGetSymbolAddress((void**)&prl, g_rl);

    embed_kernel<<<(NM * NE + 255) / 256, 256>>>(x0, wte, wpe, px);

    for (int l = 0; l < NL; ++l) {
        ln_kernel<<<NM, 256>>>(px, ln1w + (size_t)l * NE, ln1b + (size_t)l * NE, ph);
        gemm_kernel<0, false><<<dim3(N3 / 64, NM / 64), 256>>>(
            ph, Wqkv + (size_t)l * NE * N3, pq, nullptr, NM, N3, NE);
        attn_scores<<<dim3(NTOK / 64, NTOK / 64, NB * NH), 256>>>(pq, pa);
        attn_softmax<<<NB * NH * NTOK, 256>>>(pa);
        attn_av<<<dim3(NTOK / 64, NB * NH), 256>>>(pa, pq, py);
        gemm_kernel<1, false><<<dim3(NE / 64, NM / 64), 256>>>(
            py, Wo + (size_t)l * NE * NE, px, px, NM, NE, NE);
        ln_kernel<<<NM, 256>>>(px, ln2w + (size_t)l * NE, ln2b + (size_t)l * NE, ph);
        gemm_kernel<2, false><<<dim3(N4 / 64, NM / 64), 256>>>(
            ph, Wfc + (size_t)l * NE * N4, pf, nullptr, NM, N4, NE);
        gemm_kernel<1, false><<<dim3(NE / 64, NM / 64), 256>>>(
            pf, Wproj + (size_t)l * N4 * NE, px, px, NM, NE, N4);
    }

    ln_kernel<<<NM, 256>>>(px, lnfw, lnfb, ph);

    const size_t logits_elems = (size_t)NM * NV;
    float* logits = ((size_t)out_size >= logits_elems) ? (float*)d_out : pl;
    gemm_kernel<0, true><<<dim3((NV + 63) / 64, NM / 64), 256>>>(
        ph, wte, logits, nullptr, NM, NV, NE);

    loss_rows<<<NM, 256>>>(logits, tgt, prl);
    if ((size_t)out_size > logits_elems) {
        loss_final<<<1, 256>>>(prl, (float*)d_out + logits_elems);
    } else if (logits != (float*)d_out) {
        loss_final<<<1, 256>>>(prl, (float*)d_out);
    }
}

// round 2
// speedup vs baseline: 1.7213x; 1.7213x over previous
#include <cuda_runtime.h>
#include <cuda_bf16.h>
#include <math.h>
#include <stdint.h>

// GPT-2 small fwd: B=2 T=1024 E=768 H=12 L=6 V=50257
#define NB 2
#define NTOK 1024
#define NE 768
#define NH 12
#define DH 64
#define NL 6
#define NV 50257
#define NM (NB*NTOK)     // 2048 tokens
#define N3 (3*NE)        // 2304
#define N4 (4*NE)        // 3072

// transposed-weight element counts (per layer)
#define LQKV (N3*NE)
#define LWO  (NE*NE)
#define LWFC (N4*NE)
#define LWPR (NE*N4)
#define LPL  (LQKV+LWO+LWFC+LWPR)

// ---------------- scratch (device globals; no allocation allowed) -------------
static __device__ float g_x  [NM*NE];
static __device__ float g_h  [NM*NE];
static __device__ float g_qkv[NM*N3];
static __device__ float g_att[(size_t)NB*NH*NTOK*NTOK];
static __device__ float g_y  [NM*NE];
static __device__ float g_fc [NM*N4];
static __device__ float g_logits[(size_t)NM*NV];
static __device__ float g_rl [NM];
// bf16 split scratch
static __device__ __nv_bfloat16 g_wth[(size_t)NL*LPL];   // transposed weights hi
static __device__ __nv_bfloat16 g_wtl[(size_t)NL*LPL];   // transposed weights lo
static __device__ __nv_bfloat16 g_wteh[(size_t)NV*NE];
static __device__ __nv_bfloat16 g_wtel[(size_t)NV*NE];
static __device__ __nv_bfloat16 g_ah[(size_t)NM*N4];     // activation hi (max size)
static __device__ __nv_bfloat16 g_al[(size_t)NM*N4];     // activation lo

// ---------------- embed ---------------------------------------------------------
__global__ void embed_kernel(const int* __restrict__ x0,
                             const float* __restrict__ wte,
                             const float* __restrict__ wpe,
                             float* __restrict__ x) {
    int i = blockIdx.x * blockDim.x + threadIdx.x;
    if (i >= NM * NE) return;
    int tok = i / NE, e = i - tok * NE;
    int t = tok % NTOK;
    int id = x0[tok];
    x[i] = wte[(size_t)id * NE + e] + wpe[(size_t)t * NE + e];
}

// ---------------- layernorm -----------------------------------------------------
__global__ void __launch_bounds__(256) ln_kernel(const float* __restrict__ x,
                                                 const float* __restrict__ w,
                                                 const float* __restrict__ b,
                                                 float* __restrict__ out) {
    int tok = blockIdx.x;
    const float* row = x + (size_t)tok * NE;
    __shared__ float red[256];
    int tid = threadIdx.x;

    float s = 0.f;
    for (int e = tid; e < NE; e += 256) s += row[e];
    red[tid] = s; __syncthreads();
    for (int o = 128; o > 0; o >>= 1) { if (tid < o) red[tid] += red[tid + o]; __syncthreads(); }
    float mean = red[0] * (1.0f / NE);
    __syncthreads();

    float v = 0.f;
    for (int e = tid; e < NE; e += 256) { float d = row[e] - mean; v += d * d; }
    red[tid] = v; __syncthreads();
    for (int o = 128; o > 0; o >>= 1) { if (tid < o) red[tid] += red[tid + o]; __syncthreads(); }
    float rstd = rsqrtf(red[0] * (1.0f / NE) + 1e-6f);

    for (int e = tid; e < NE; e += 256)
        out[(size_t)tok * NE + e] = (row[e] - mean) * rstd * w[e] + b[e];
}

// ---------------- split fp32 -> (hi, lo) bf16 -----------------------------------
__global__ void split_kernel(const float* __restrict__ x,
                             __nv_bfloat16* __restrict__ hi,
                             __nv_bfloat16* __restrict__ lo, int n) {
    int i = blockIdx.x * blockDim.x + threadIdx.x;
    if (i >= n) return;
    float v = x[i];
    __nv_bfloat16 h = __float2bfloat16(v);
    hi[i] = h;
    lo[i] = __float2bfloat16(v - __bfloat162float(h));
}

// ---------------- transpose-split: in[K,N] fp32 -> out[N,K] bf16 hi/lo ----------
__global__ void tsplit_kernel(const float* __restrict__ in,
                              __nv_bfloat16* __restrict__ oh,
                              __nv_bfloat16* __restrict__ ol,
                              int K, int N) {
    __shared__ float tile[32][33];
    int k = blockIdx.y * 32 + threadIdx.y;
    int n = blockIdx.x * 32 + threadIdx.x;
    if (k < K && n < N) tile[threadIdx.y][threadIdx.x] = in[(size_t)k * N + n];
    __syncthreads();
    int on = blockIdx.x * 32 + threadIdx.y;
    int ok = blockIdx.y * 32 + threadIdx.x;
    if (on < N && ok < K) {
        float v = tile[threadIdx.x][threadIdx.y];
        __nv_bfloat16 h = __float2bfloat16(v);
        oh[(size_t)on * K + ok] = h;
        ol[(size_t)on * K + ok] = __float2bfloat16(v - __bfloat162float(h));
    }
}

// ---------------- split-bf16 tensor-core GEMM ------------------------------------
// C[M,N] = epi( A[M,K] * B^T where B stored [N,K] ), A,B pre-split into hi/lo bf16.
// EPI: 0 none, 1 residual (C = R + AB), 2 gelu(AB)
__device__ __forceinline__ float gelu_tanh(float x) {
    const float c = 0.7978845608028654f;
    float x3 = x * x * x;
    return 0.5f * x * (1.0f + tanhf(c * (x + 0.044715f * x3)));
}

#define MMA16816(c, a, b) \
    asm volatile("mma.sync.aligned.m16n8k16.row.col.f32.bf16.bf16.f32 " \
                 "{%0,%1,%2,%3}, {%4,%5,%6,%7}, {%8,%9}, {%0,%1,%2,%3};" \
                 : "+f"((c)[0]), "+f"((c)[1]), "+f"((c)[2]), "+f"((c)[3]) \
                 : "r"((a)[0]), "r"((a)[1]), "r"((a)[2]), "r"((a)[3]), \
                   "r"((b)[0]), "r"((b)[1]))

template<int EPI>
__global__ void __launch_bounds__(256) gemm_bf16s(
    const __nv_bfloat16* __restrict__ Ah, const __nv_bfloat16* __restrict__ Al,
    const __nv_bfloat16* __restrict__ Bh, const __nv_bfloat16* __restrict__ Bl,
    float* __restrict__ C, const float* __restrict__ R,
    int M, int N, int K)
{
    // BM=128, BN=64, BK=32; 8 warps as 4(m) x 2(n); warp tile 32x32
    __shared__ __nv_bfloat16 Ash[128][40];
    __shared__ __nv_bfloat16 Asl[128][40];
    __shared__ __nv_bfloat16 Bsh[64][40];
    __shared__ __nv_bfloat16 Bsl[64][40];

    const int tid  = threadIdx.x;
    const int lane = tid & 31, wid = tid >> 5;
    const int wm = wid >> 1, wn = wid & 1;
    const int g = lane >> 2, tg = lane & 3;
    const int m0 = blockIdx.y * 128;
    const int n0 = blockIdx.x * 64;

    const int ar = tid >> 2;           // 0..63
    const int aq = (tid & 3) * 8;      // bf16 col offset

    float acc[2][4][4];
#pragma unroll
    for (int a = 0; a < 2; ++a)
#pragma unroll
        for (int b = 0; b < 4; ++b)
#pragma unroll
            for (int c = 0; c < 4; ++c) acc[a][b][c] = 0.f;

    const float4 z4 = make_float4(0.f, 0.f, 0.f, 0.f);

    for (int k0 = 0; k0 < K; k0 += 32) {
        // A tile (rows always in-bounds: M % 128 == 0)
        *(float4*)&Ash[ar][aq]      = *(const float4*)(Ah + (size_t)(m0 + ar) * K + k0 + aq);
        *(float4*)&Ash[ar + 64][aq] = *(const float4*)(Ah + (size_t)(m0 + ar + 64) * K + k0 + aq);
        *(float4*)&Asl[ar][aq]      = *(const float4*)(Al + (size_t)(m0 + ar) * K + k0 + aq);
        *(float4*)&Asl[ar + 64][aq] = *(const float4*)(Al + (size_t)(m0 + ar + 64) * K + k0 + aq);
        // B tile (guard N tail)
        {
            int n = n0 + ar;
            if (n < N) {
                *(float4*)&Bsh[ar][aq] = *(const float4*)(Bh + (size_t)n * K + k0 + aq);
                *(float4*)&Bsl[ar][aq] = *(const float4*)(Bl + (size_t)n * K + k0 + aq);
            } else {
                *(float4*)&Bsh[ar][aq] = z4;
                *(float4*)&Bsl[ar][aq] = z4;
            }
        }
        __syncthreads();

#pragma unroll
        for (int kk = 0; kk < 32; kk += 16) {
            uint32_t ah[2][4], al[2][4], bh[4][2], bl[4][2];
#pragma unroll
            for (int mt = 0; mt < 2; ++mt) {
                int rb = wm * 32 + mt * 16;
                ah[mt][0] = *(const uint32_t*)&Ash[rb + g    ][kk + 2 * tg];
                ah[mt][1] = *(const uint32_t*)&Ash[rb + g + 8][kk + 2 * tg];
                ah[mt][2] = *(const uint32_t*)&Ash[rb + g    ][kk + 8 + 2 * tg];
                ah[mt][3] = *(const uint32_t*)&Ash[rb + g + 8][kk + 8 + 2 * tg];
                al[mt][0] = *(const uint32_t*)&Asl[rb + g    ][kk + 2 * tg];
                al[mt][1] = *(const uint32_t*)&Asl[rb + g + 8][kk + 2 * tg];
                al[mt][2] = *(const uint32_t*)&Asl[rb + g    ][kk + 8 + 2 * tg];
                al[mt][3] = *(const uint32_t*)&Asl[rb + g + 8][kk + 8 + 2 * tg];
            }
#pragma unroll
            for (int nt = 0; nt < 4; ++nt) {
                int cb = wn * 32 + nt * 8;
                bh[nt][0] = *(const uint32_t*)&Bsh[cb + g][kk + 2 * tg];
                bh[nt][1] = *(const uint32_t*)&Bsh[cb + g][kk + 8 + 2 * tg];
                bl[nt][0] = *(const uint32_t*)&Bsl[cb + g][kk + 2 * tg];
                bl[nt][1] = *(const uint32_t*)&Bsl[cb + g][kk + 8 + 2 * tg];
            }
#pragma unroll
            for (int mt = 0; mt < 2; ++mt)
#pragma unroll
                for (int nt = 0; nt < 4; ++nt) {
                    MMA16816(acc[mt][nt], ah[mt], bh[nt]);
                    MMA16816(acc[mt][nt], ah[mt], bl[nt]);
                    MMA16816(acc[mt][nt], al[mt], bh[nt]);
                }
        }
        __syncthreads();
    }

    // epilogue
#pragma unroll
    for (int mt = 0; mt < 2; ++mt) {
#pragma unroll
        for (int nt = 0; nt < 4; ++nt) {
            int nbase = n0 + wn * 32 + nt * 8 + 2 * tg;
#pragma unroll
            for (int r = 0; r < 2; ++r) {
                int m = m0 + wm * 32 + mt * 16 + g + 8 * r;
                float v0 = acc[mt][nt][2 * r + 0];
                float v1 = acc[mt][nt][2 * r + 1];
                if (EPI == 1) {
                    if (nbase     < N) v0 += R[(size_t)m * N + nbase];
                    if (nbase + 1 < N) v1 += R[(size_t)m * N + nbase + 1];
                }
                if (EPI == 2) { v0 = gelu_tanh(v0); v1 = gelu_tanh(v1); }
                if (nbase     < N) C[(size_t)m * N + nbase]     = v0;
                if (nbase + 1 < N) C[(size_t)m * N + nbase + 1] = v1;
            }
        }
    }
}

// ---------------- attention: scores S = Q K^T * scale ----------------------------
__global__ void __launch_bounds__(256) attn_scores(const float* __restrict__ qkv,
                                                   float* __restrict__ att) {
    if (blockIdx.x > blockIdx.y) return;
    int bh = blockIdx.z;
    int b = bh / NH, h = bh % NH;
    int t0 = blockIdx.y * 64, s0 = blockIdx.x * 64;
    __shared__ float Qs[64][68];
    __shared__ float Ks[64][68];
    int tid = threadIdx.x;

#pragma unroll
    for (int i = 0; i < 4; ++i) {
        int l = tid + i * 256;
        int r = l >> 4;
        int dq = (l & 15) * 4;
        float4 q = *(const float4*)(qkv + (size_t)(b * NTOK + t0 + r) * N3 + h * DH + dq);
        Qs[dq+0][r] = q.x; Qs[dq+1][r] = q.y; Qs[dq+2][r] = q.z; Qs[dq+3][r] = q.w;
        float4 k = *(const float4*)(qkv + (size_t)(b * NTOK + s0 + r) * N3 + NE + h * DH + dq);
        Ks[dq+0][r] = k.x; Ks[dq+1][r] = k.y; Ks[dq+2][r] = k.z; Ks[dq+3][r] = k.w;
    }
    __syncthreads();

    int ty = tid >> 4, tx = tid & 15;
    float acc[4][4] = {};
#pragma unroll
    for (int d = 0; d < 64; ++d) {
        float4 a = *(const float4*)&Qs[d][ty * 4];
        float4 b4 = *(const float4*)&Ks[d][tx * 4];
        float av[4] = {a.x, a.y, a.z, a.w};
        float bv[4] = {b4.x, b4.y, b4.z, b4.w};
#pragma unroll
        for (int i = 0; i < 4; ++i)
#pragma unroll
            for (int j = 0; j < 4; ++j)
                acc[i][j] = fmaf(av[i], bv[j], acc[i][j]);
    }
    const float scale = 0.125f;
#pragma unroll
    for (int i = 0; i < 4; ++i) {
        int t = t0 + ty * 4 + i;
#pragma unroll
        for (int j = 0; j < 4; ++j) {
            int s = s0 + tx * 4 + j;
            att[((size_t)bh * NTOK + t) * NTOK + s] = acc[i][j] * scale;
        }
    }
}

// ---------------- causal softmax -------------------------------------------------
__global__ void __launch_bounds__(256) attn_softmax(float* __restrict__ att) {
    int row = blockIdx.x;
    int t = row % NTOK;
    float* p = att + (size_t)row * NTOK;
    int n = t + 1;
    __shared__ float red[256];
    int tid = threadIdx.x;

    float m = -INFINITY;
    for (int s = tid; s < n; s += 256) m = fmaxf(m, p[s]);
    red[tid] = m; __syncthreads();
    for (int o = 128; o > 0; o >>= 1) { if (tid < o) red[tid] = fmaxf(red[tid], red[tid + o]); __syncthreads(); }
    m = red[0];
    __syncthreads();

    float s0 = 0.f;
    for (int s = tid; s < n; s += 256) s0 += expf(p[s] - m);
    red[tid] = s0; __syncthreads();
    for (int o = 128; o > 0; o >>= 1) { if (tid < o) red[tid] += red[tid + o]; __syncthreads(); }
    float inv = 1.0f / red[0];

    for (int s = tid; s < NTOK; s += 256)
        p[s] = (s < n) ? expf(p[s] - m) * inv : 0.0f;
}

// ---------------- attention: Y = P V ---------------------------------------------
__global__ void __launch_bounds__(256) attn_av(const float* __restrict__ att,
                                               const float* __restrict__ qkv,
                                               float* __restrict__ y) {
    int bh = blockIdx.y;
    int b = bh / NH, h = bh % NH;
    int t0 = blockIdx.x * 64;
    __shared__ float Ps[64][68];
    __shared__ float Vs[64][68];
    int tid = threadIdx.x;
    int ty = tid >> 4, tx = tid & 15;
    float acc[4][4] = {};

    for (int c = 0; c <= blockIdx.x; ++c) {
        int s0 = c * 64;
#pragma unroll
        for (int i = 0; i < 4; ++i) {
            int l = tid + i * 256;
            int r = l >> 4;
            int q = (l & 15) * 4;
            float4 pv = *(const float4*)(att + ((size_t)bh * NTOK + t0 + r) * NTOK + s0 + q);
            Ps[q+0][r] = pv.x; Ps[q+1][r] = pv.y; Ps[q+2][r] = pv.z; Ps[q+3][r] = pv.w;
            float4 vv = *(const float4*)(qkv + (size_t)(b * NTOK + s0 + r) * N3 + 2 * NE + h * DH + q);
            *(float4*)&Vs[r][q] = vv;
        }
        __syncthreads();
#pragma unroll
        for (int s = 0; s < 64; ++s) {
            float4 a = *(const float4*)&Ps[s][ty * 4];
            float4 b4 = *(const float4*)&Vs[s][tx * 4];
            float av[4] = {a.x, a.y, a.z, a.w};
            float bv[4] = {b4.x, b4.y, b4.z, b4.w};
#pragma unroll
            for (int i = 0; i < 4; ++i)
#pragma unroll
                for (int j = 0; j < 4; ++j)
                    acc[i][j] = fmaf(av[i], bv[j], acc[i][j]);
        }
        __syncthreads();
    }
#pragma unroll
    for (int i = 0; i < 4; ++i) {
        int t = t0 + ty * 4 + i;
#pragma unroll
        for (int j = 0; j < 4; ++j) {
            int d = tx * 4 + j;
            y[(size_t)(b * NTOK + t) * NE + h * DH + d] = acc[i][j];
        }
    }
}

// ---------------- loss ------------------------------------------------------------
__global__ void __launch_bounds__(256) loss_rows(const float* __restrict__ logits,
                                                 const int* __restrict__ tgt,
                                                 float* __restrict__ rl) {
    int row = blockIdx.x;
    const float* p = logits + (size_t)row * NV;
    __shared__ float sm[256], ss[256];
    int tid = threadIdx.x;

    float m = -INFINITY, s = 0.f;
    for (int j = tid; j < NV; j += 256) {
        float v = p[j];
        float nm = fmaxf(m, v);
        s = s * expf(m - nm) + expf(v - nm);
        m = nm;
    }
    sm[tid] = m; ss[tid] = s; __syncthreads();
    for (int o = 128; o > 0; o >>= 1) {
        if (tid < o) {
            float m2 = sm[tid + o], s2 = ss[tid + o];
            float M = fmaxf(sm[tid], m2);
            ss[tid] = ss[tid] * expf(sm[tid] - M) + s2 * expf(m2 - M);
            sm[tid] = M;
        }
        __syncthreads();
    }
    if (tid == 0) {
        float lt = p[tgt[row]];
        rl[row] = -(lt - sm[0] - logf(ss[0]));
    }
}

__global__ void __launch_bounds__(256) loss_final(const float* __restrict__ rl,
                                                  float* __restrict__ out) {
    __shared__ float red[256];
    int tid = threadIdx.x;
    float s = 0.f;
    for (int i = tid; i < NM; i += 256) s += rl[i];
    red[tid] = s; __syncthreads();
    for (int o = 128; o > 0; o >>= 1) { if (tid < o) red[tid] += red[tid + o]; __syncthreads(); }
    if (tid == 0) out[0] = red[0] * (1.0f / NM);
}

// ---------------- host orchestration -----------------------------------------------
extern "C" void kernel_launch(void* const* d_in, const int* in_sizes, int n_in,
                              void* d_out, int out_size) {
    const int*   x0    = (const int*)  d_in[0];
    const int*   tgt   = (const int*)  d_in[1];
    const float* wte   = (const float*)d_in[2];
    const float* wpe   = (const float*)d_in[3];
    const float* ln1w  = (const float*)d_in[4];
    const float* ln1b  = (const float*)d_in[5];
    const float* Wqkv  = (const float*)d_in[6];
    const float* Wo    = (const float*)d_in[7];
    const float* ln2w  = (const float*)d_in[8];
    const float* ln2b  = (const float*)d_in[9];
    const float* Wfc   = (const float*)d_in[10];
    const float* Wproj = (const float*)d_in[11];
    const float* lnfw  = (const float*)d_in[12];
    const float* lnfb  = (const float*)d_in[13];

    float *px, *ph, *pq, *pa, *py, *pf, *pl, *prl;
    __nv_bfloat16 *pwth, *pwtl, *pwteh, *pwtel, *pah, *pal;
    cudaGetSymbolAddress((void**)&px,  g_x);
    cudaGetSymbolAddress((void**)&ph,  g_h);
    cudaGetSymbolAddress((void**)&pq,  g_qkv);
    cudaGetSymbolAddress((void**)&pa,  g_att);
    cudaGetSymbolAddress((void**)&py,  g_y);
    cudaGetSymbolAddress((void**)&pf,  g_fc);
    cudaGetSymbolAddress((void**)&pl,  g_logits);
    cudaGetSymbolAddress((void**)&prl, g_rl);
    cudaGetSymbolAddress((void**)&pwth, g_wth);
    cudaGetSymbolAddress((void**)&pwtl, g_wtl);
    cudaGetSymbolAddress((void**)&pwteh, g_wteh);
    cudaGetSymbolAddress((void**)&pwtel, g_wtel);
    cudaGetSymbolAddress((void**)&pah, g_ah);
    cudaGetSymbolAddress((void**)&pal, g_al);

    dim3 t32(32, 32);

    // weight transpose+split (per launch; independent of activations)
    for (int l = 0; l < NL; ++l) {
        size_t off = (size_t)l * LPL;
        tsplit_kernel<<<dim3(N3 / 32, NE / 32), t32>>>(
            Wqkv + (size_t)l * NE * N3, pwth + off, pwtl + off, NE, N3);
        off += LQKV;
        tsplit_kernel<<<dim3(NE / 32, NE / 32), t32>>>(
            Wo + (size_t)l * NE * NE, pwth + off, pwtl + off, NE, NE);
        off += LWO;
        tsplit_kernel<<<dim3(N4 / 32, NE / 32), t32>>>(
            Wfc + (size_t)l * NE * N4, pwth + off, pwtl + off, NE, N4);
        off += LWFC;
        tsplit_kernel<<<dim3(NE / 32, N4 / 32), t32>>>(
            Wproj + (size_t)l * N4 * NE, pwth + off, pwtl + off, N4, NE);
    }
    // wte split (already [V, E] = [N, K])
    split_kernel<<<((size_t)NV * NE + 255) / 256, 256>>>(wte, pwteh, pwtel, NV * NE);

    embed_kernel<<<(NM * NE + 255) / 256, 256>>>(x0, wte, wpe, px);

    for (int l = 0; l < NL; ++l) {
        size_t off = (size_t)l * LPL;
        // ln1 -> split -> QKV gemm
        ln_kernel<<<NM, 256>>>(px, ln1w + (size_t)l * NE, ln1b + (size_t)l * NE, ph);
        split_kernel<<<(NM * NE + 255) / 256, 256>>>(ph, pah, pal, NM * NE);
        gemm_bf16s<0><<<dim3(N3 / 64, NM / 128), 256>>>(
            pah, pal, pwth + off, pwtl + off, pq, nullptr, NM, N3, NE);
        // attention (fp32)
        attn_scores<<<dim3(NTOK / 64, NTOK / 64, NB * NH), 256>>>(pq, pa);
        attn_softmax<<<NB * NH * NTOK, 256>>>(pa);
        attn_av<<<dim3(NTOK / 64, NB * NH), 256>>>(pa, pq, py);
        // Wo gemm + residual
        split_kernel<<<(NM * NE + 255) / 256, 256>>>(py, pah, pal, NM * NE);
        gemm_bf16s<1><<<dim3(NE / 64, NM / 128), 256>>>(
            pah, pal, pwth + off + LQKV, pwtl + off + LQKV, px, px, NM, NE, NE);
        // ln2 -> FC gemm (gelu)
        ln_kernel<<<NM, 256>>>(px, ln2w + (size_t)l * NE, ln2b + (size_t)l * NE, ph);
        split_kernel<<<(NM * NE + 255) / 256, 256>>>(ph, pah, pal, NM * NE);
        gemm_bf16s<2><<<dim3(N4 / 64, NM / 128), 256>>>(
            pah, pal, pwth + off + LQKV + LWO, pwtl + off + LQKV + LWO, pf, nullptr, NM, N4, NE);
        // Proj gemm + residual
        split_kernel<<<(NM * N4 + 255) / 256, 256>>>(pf, pah, pal, NM * N4);
        gemm_bf16s<1><<<dim3(NE / 64, NM / 128), 256>>>(
            pah, pal, pwth + off + LQKV + LWO + LWFC, pwtl + off + LQKV + LWO + LWFC,
            px, px, NM, NE, N4);
    }

    ln_kernel<<<NM, 256>>>(px, lnfw, lnfb, ph);
    split_kernel<<<(NM * NE + 255) / 256, 256>>>(ph, pah, pal, NM * NE);

    const size_t logits_elems = (size_t)NM * NV;
    float* logits = ((size_t)out_size >= logits_elems) ? (float*)d_out : pl;
    gemm_bf16s<0><<<dim3((NV + 63) / 64, NM / 128), 256>>>(
        pah, pal, pwteh, pwtel, logits, nullptr, NM, NV, NE);

    loss_rows<<<NM, 256>>>(logits, tgt, prl);
    if ((size_t)out_size > logits_elems) {
        loss_final<<<1, 256>>>(prl, (float*)d_out + logits_elems);
    } else if (logits != (float*)d_out) {
        loss_final<<<1, 256>>>(prl, (float*)d_out);
    }
}

// round 3
// speedup vs baseline: 2.3673x; 1.3753x over previous
#include <cuda_runtime.h>
#include <cuda_bf16.h>
#include <math.h>
#include <stdint.h>

// GPT-2 small fwd: B=2 T=1024 E=768 H=12 L=6 V=50257
#define NB 2
#define NTOK 1024
#define NE 768
#define NH 12
#define DH 64
#define NL 6
#define NV 50257
#define NM (NB*NTOK)
#define N3 (3*NE)
#define N4 (4*NE)

#define LQKV (N3*NE)
#define LWO  (NE*NE)
#define LWFC (N4*NE)
#define LWPR (NE*N4)
#define LPL  (LQKV+LWO+LWFC+LWPR)

typedef __nv_bfloat16 bf16;

// ---------------- scratch ------------------------------------------------------
static __device__ float g_x  [NM*NE];
static __device__ float g_logits[(size_t)NM*NV];
static __device__ float g_rl [NM];
static __device__ bf16 g_wth[(size_t)NL*LPL];
static __device__ bf16 g_wtl[(size_t)NL*LPL];
static __device__ bf16 g_wteh[(size_t)NV*NE];
static __device__ bf16 g_wtel[(size_t)NV*NE];
static __device__ bf16 g_lnh[NM*NE];
static __device__ bf16 g_lnl[NM*NE];
static __device__ bf16 g_qkvh[NM*N3];
static __device__ bf16 g_qkvl[NM*N3];
static __device__ bf16 g_yh[NM*NE];
static __device__ bf16 g_yl[NM*NE];
static __device__ bf16 g_fch[NM*N4];
static __device__ bf16 g_fcl[NM*N4];

// ---------------- helpers -------------------------------------------------------
__device__ __forceinline__ uint32_t packbf(float a, float b) {
    __nv_bfloat162 t;
    t.x = __float2bfloat16(a);
    t.y = __float2bfloat16(b);
    return *(uint32_t*)&t;
}

__device__ __forceinline__ void cpa16(void* dst, const void* src) {
    uint32_t d = (uint32_t)__cvta_generic_to_shared(dst);
    asm volatile("cp.async.cg.shared.global [%0], [%1], 16;" :: "r"(d), "l"(src));
}
__device__ __forceinline__ void cpa16z(void* dst, const void* src, int sz) {
    uint32_t d = (uint32_t)__cvta_generic_to_shared(dst);
    asm volatile("cp.async.cg.shared.global [%0], [%1], 16, %2;" :: "r"(d), "l"(src), "r"(sz));
}
#define CP_COMMIT() asm volatile("cp.async.commit_group;")
#define CP_WAIT(n)  asm volatile("cp.async.wait_group %0;" :: "n"(n))

#define MMA16816(c, a, b) \
    asm volatile("mma.sync.aligned.m16n8k16.row.col.f32.bf16.bf16.f32 " \
                 "{%0,%1,%2,%3}, {%4,%5,%6,%7}, {%8,%9}, {%0,%1,%2,%3};" \
                 : "+f"((c)[0]), "+f"((c)[1]), "+f"((c)[2]), "+f"((c)[3]) \
                 : "r"((a)[0]), "r"((a)[1]), "r"((a)[2]), "r"((a)[3]), \
                   "r"((b)[0]), "r"((b)[1]))

__device__ __forceinline__ float gelu_tanh(float x) {
    const float c = 0.7978845608028654f;
    float x3 = x * x * x;
    return 0.5f * x * (1.0f + tanhf(c * (x + 0.044715f * x3)));
}

// ---------------- embed ---------------------------------------------------------
__global__ void embed_kernel(const int* __restrict__ x0,
                             const float* __restrict__ wte,
                             const float* __restrict__ wpe,
                             float* __restrict__ x) {
    int i = blockIdx.x * blockDim.x + threadIdx.x;
    if (i >= NM * NE) return;
    int tok = i / NE, e = i - tok * NE;
    int t = tok % NTOK;
    int id = x0[tok];
    x[i] = wte[(size_t)id * NE + e] + wpe[(size_t)t * NE + e];
}

// ---------------- layernorm -> split bf16 ----------------------------------------
__global__ void __launch_bounds__(256) ln_split(const float* __restrict__ x,
                                                const float* __restrict__ w,
                                                const float* __restrict__ b,
                                                bf16* __restrict__ oh,
                                                bf16* __restrict__ ol) {
    int tok = blockIdx.x;
    const float* row = x + (size_t)tok * NE;
    __shared__ float red[256];
    int tid = threadIdx.x;

    float s = 0.f;
    for (int e = tid; e < NE; e += 256) s += row[e];
    red[tid] = s; __syncthreads();
    for (int o = 128; o > 0; o >>= 1) { if (tid < o) red[tid] += red[tid + o]; __syncthreads(); }
    float mean = red[0] * (1.0f / NE);
    __syncthreads();

    float v = 0.f;
    for (int e = tid; e < NE; e += 256) { float d = row[e] - mean; v += d * d; }
    red[tid] = v; __syncthreads();
    for (int o = 128; o > 0; o >>= 1) { if (tid < o) red[tid] += red[tid + o]; __syncthreads(); }
    float rstd = rsqrtf(red[0] * (1.0f / NE) + 1e-6f);

    for (int e = tid; e < NE; e += 256) {
        float val = (row[e] - mean) * rstd * w[e] + b[e];
        bf16 h = __float2bfloat16(val);
        oh[(size_t)tok * NE + e] = h;
        ol[(size_t)tok * NE + e] = __float2bfloat16(val - __bfloat162float(h));
    }
}

// ---------------- splits for weights ---------------------------------------------
__global__ void split_kernel(const float* __restrict__ x,
                             bf16* __restrict__ hi, bf16* __restrict__ lo, int n) {
    int i = blockIdx.x * blockDim.x + threadIdx.x;
    if (i >= n) return;
    float v = x[i];
    bf16 h = __float2bfloat16(v);
    hi[i] = h;
    lo[i] = __float2bfloat16(v - __bfloat162float(h));
}

__global__ void tsplit_kernel(const float* __restrict__ in,
                              bf16* __restrict__ oh, bf16* __restrict__ ol,
                              int K, int N) {
    __shared__ float tile[32][33];
    int k = blockIdx.y * 32 + threadIdx.y;
    int n = blockIdx.x * 32 + threadIdx.x;
    if (k < K && n < N) tile[threadIdx.y][threadIdx.x] = in[(size_t)k * N + n];
    __syncthreads();
    int on = blockIdx.x * 32 + threadIdx.y;
    int ok = blockIdx.y * 32 + threadIdx.x;
    if (on < N && ok < K) {
        float v = tile[threadIdx.x][threadIdx.y];
        bf16 h = __float2bfloat16(v);
        oh[(size_t)on * K + ok] = h;
        ol[(size_t)on * K + ok] = __float2bfloat16(v - __bfloat162float(h));
    }
}

// ---------------- GEMM v2: double-buffered cp.async split-bf16 HMMA ---------------
// C = epi(A[M,K] * B^T), B stored [N,K]. EPI: 0 none, 1 +R, 2 gelu.
// OUT: 0 fp32 C, 1 bf16 hi/lo pair (Ch, Cl). WM = warps in M (2 -> BN=128, 4 -> BN=64).
template<int EPI, int OUT, int WM>
__global__ void __launch_bounds__(256) gemm2(
    const bf16* __restrict__ Ah, const bf16* __restrict__ Al,
    const bf16* __restrict__ Bh, const bf16* __restrict__ Bl,
    float* __restrict__ C, bf16* __restrict__ Ch, bf16* __restrict__ Cl,
    const float* __restrict__ R, int M, int N, int K)
{
    constexpr int WN = 8 / WM;
    constexpr int BN = WN * 32;
    constexpr int MT = 128 / (16 * WM);   // m-frags per warp
    extern __shared__ bf16 smem[];
    bf16* Ash = smem;                    // [2][128][40]
    bf16* Asl = Ash + 2 * 128 * 40;
    bf16* Bsh = Asl + 2 * 128 * 40;      // [2][BN][40]
    bf16* Bsl = Bsh + 2 * BN * 40;

    const int tid = threadIdx.x;
    const int lane = tid & 31, wid = tid >> 5;
    const int wm = wid / WN, wn = wid % WN;
    const int g = lane >> 2, tg = lane & 3;
    const int m0 = blockIdx.y * 128;
    const int n0 = blockIdx.x * BN;

    float acc[MT][4][4];
#pragma unroll
    for (int a = 0; a < MT; ++a)
#pragma unroll
        for (int b = 0; b < 4; ++b)
#pragma unroll
            for (int c = 0; c < 4; ++c) acc[a][b][c] = 0.f;

    auto load_stage = [&](int st, int k0) {
#pragma unroll
        for (int i = 0; i < 2; ++i) {
            int c = tid + 256 * i;
            int r = c >> 2, cq = (c & 3) * 8;
            cpa16(&Ash[(st * 128 + r) * 40 + cq], Ah + (size_t)(m0 + r) * K + k0 + cq);
            cpa16(&Asl[(st * 128 + r) * 40 + cq], Al + (size_t)(m0 + r) * K + k0 + cq);
        }
        for (int c = tid; c < BN * 4; c += 256) {
            int r = c >> 2, cq = (c & 3) * 8;
            int n = n0 + r;
            int ok = n < N;
            size_t src = (size_t)(ok ? n : 0) * K + k0 + cq;
            cpa16z(&Bsh[(st * BN + r) * 40 + cq], Bh + src, ok ? 16 : 0);
            cpa16z(&Bsl[(st * BN + r) * 40 + cq], Bl + src, ok ? 16 : 0);
        }
    };

    load_stage(0, 0);
    CP_COMMIT();
    const int nk = K / 32;
    for (int it = 0; it < nk; ++it) {
        int st = it & 1;
        if (it + 1 < nk) { load_stage(st ^ 1, (it + 1) * 32); CP_COMMIT(); CP_WAIT(1); }
        else            { CP_WAIT(0); }
        __syncthreads();
#pragma unroll
        for (int kk = 0; kk < 32; kk += 16) {
            uint32_t ah[MT][4], al[MT][4];
#pragma unroll
            for (int mt = 0; mt < MT; ++mt) {
                int rb = st * 128 + wm * MT * 16 + mt * 16;
                ah[mt][0] = *(const uint32_t*)&Ash[(rb + g    ) * 40 + kk + 2 * tg];
                ah[mt][1] = *(const uint32_t*)&Ash[(rb + g + 8) * 40 + kk + 2 * tg];
                ah[mt][2] = *(const uint32_t*)&Ash[(rb + g    ) * 40 + kk + 8 + 2 * tg];
                ah[mt][3] = *(const uint32_t*)&Ash[(rb + g + 8) * 40 + kk + 8 + 2 * tg];
                al[mt][0] = *(const uint32_t*)&Asl[(rb + g    ) * 40 + kk + 2 * tg];
                al[mt][1] = *(const uint32_t*)&Asl[(rb + g + 8) * 40 + kk + 2 * tg];
                al[mt][2] = *(const uint32_t*)&Asl[(rb + g    ) * 40 + kk + 8 + 2 * tg];
                al[mt][3] = *(const uint32_t*)&Asl[(rb + g + 8) * 40 + kk + 8 + 2 * tg];
            }
            uint32_t bhf[4][2], blf[4][2];
#pragma unroll
            for (int nt = 0; nt < 4; ++nt) {
                int cb = st * BN + wn * 32 + nt * 8;
                bhf[nt][0] = *(const uint32_t*)&Bsh[(cb + g) * 40 + kk + 2 * tg];
                bhf[nt][1] = *(const uint32_t*)&Bsh[(cb + g) * 40 + kk + 8 + 2 * tg];
                blf[nt][0] = *(const uint32_t*)&Bsl[(cb + g) * 40 + kk + 2 * tg];
                blf[nt][1] = *(const uint32_t*)&Bsl[(cb + g) * 40 + kk + 8 + 2 * tg];
            }
#pragma unroll
            for (int mt = 0; mt < MT; ++mt)
#pragma unroll
                for (int nt = 0; nt < 4; ++nt) {
                    MMA16816(acc[mt][nt], ah[mt], bhf[nt]);
                    MMA16816(acc[mt][nt], ah[mt], blf[nt]);
                    MMA16816(acc[mt][nt], al[mt], bhf[nt]);
                }
        }
        __syncthreads();
    }

    // epilogue
#pragma unroll
    for (int mt = 0; mt < MT; ++mt) {
#pragma unroll
        for (int nt = 0; nt < 4; ++nt) {
            int nbase = n0 + wn * 32 + nt * 8 + 2 * tg;
#pragma unroll
            for (int r = 0; r < 2; ++r) {
                int m = m0 + wm * MT * 16 + mt * 16 + g + 8 * r;
                float v0 = acc[mt][nt][2 * r + 0];
                float v1 = acc[mt][nt][2 * r + 1];
                if (EPI == 1) {
                    if (nbase     < N) v0 += R[(size_t)m * N + nbase];
                    if (nbase + 1 < N) v1 += R[(size_t)m * N + nbase + 1];
                }
                if (EPI == 2) { v0 = gelu_tanh(v0); v1 = gelu_tanh(v1); }
                if (OUT == 0) {
                    if (nbase     < N) C[(size_t)m * N + nbase]     = v0;
                    if (nbase + 1 < N) C[(size_t)m * N + nbase + 1] = v1;
                } else {
                    // N multiple of 128 in OUT=1 uses; no tail
                    bf16 h0 = __float2bfloat16(v0);
                    bf16 h1 = __float2bfloat16(v1);
                    float l0 = v0 - __bfloat162float(h0);
                    float l1 = v1 - __bfloat162float(h1);
                    __nv_bfloat162 hp; hp.x = h0; hp.y = h1;
                    *(uint32_t*)(Ch + (size_t)m * N + nbase) = *(uint32_t*)&hp;
                    *(uint32_t*)(Cl + (size_t)m * N + nbase) = packbf(l0, l1);
                }
            }
        }
    }
}

// ---------------- flash attention (split-bf16 MMA, causal, online softmax) --------
// grid (NTOK/64, NB*NH), 128 threads (4 warps, each owns 16 t-rows)
#define FP 72
__global__ void __launch_bounds__(128) flash_kernel(
    const bf16* __restrict__ qh, const bf16* __restrict__ ql,
    bf16* __restrict__ yh, bf16* __restrict__ yl)
{
    __shared__ bf16 Kh[64][FP], Kl[64][FP], Vh[64][FP], Vl[64][FP];
    const int bh = blockIdx.y, b = bh / NH, h = bh % NH;
    const int t0 = blockIdx.x * 64;
    const int tid = threadIdx.x, lane = tid & 31, w = tid >> 5;
    const int g = lane >> 2, tg = lane & 3;

    // stage Q tile (64x64) into Kh/Kl, then grab frags
#pragma unroll
    for (int i = 0; i < 4; ++i) {
        int c = tid + 128 * i;
        int r = c >> 3, c8 = (c & 7) * 8;
        *(float4*)&Kh[r][c8] = *(const float4*)(qh + (size_t)(b * NTOK + t0 + r) * N3 + h * DH + c8);
        *(float4*)&Kl[r][c8] = *(const float4*)(ql + (size_t)(b * NTOK + t0 + r) * N3 + h * DH + c8);
    }
    __syncthreads();
    uint32_t qfh[4][4], qfl[4][4];
    {
        int rb = w * 16;
#pragma unroll
        for (int kf = 0; kf < 4; ++kf) {
            qfh[kf][0] = *(const uint32_t*)&Kh[rb + g    ][kf * 16 + 2 * tg];
            qfh[kf][1] = *(const uint32_t*)&Kh[rb + g + 8][kf * 16 + 2 * tg];
            qfh[kf][2] = *(const uint32_t*)&Kh[rb + g    ][kf * 16 + 8 + 2 * tg];
            qfh[kf][3] = *(const uint32_t*)&Kh[rb + g + 8][kf * 16 + 8 + 2 * tg];
            qfl[kf][0] = *(const uint32_t*)&Kl[rb + g    ][kf * 16 + 2 * tg];
            qfl[kf][1] = *(const uint32_t*)&Kl[rb + g + 8][kf * 16 + 2 * tg];
            qfl[kf][2] = *(const uint32_t*)&Kl[rb + g    ][kf * 16 + 8 + 2 * tg];
            qfl[kf][3] = *(const uint32_t*)&Kl[rb + g + 8][kf * 16 + 8 + 2 * tg];
        }
    }
    __syncthreads();

    float mr[2] = {-1e30f, -1e30f};
    float lr[2] = {0.f, 0.f};
    float acco[8][4];
#pragma unroll
    for (int i = 0; i < 8; ++i)
#pragma unroll
        for (int j = 0; j < 4; ++j) acco[i][j] = 0.f;

    const int nsb = blockIdx.x + 1;
    for (int sb = 0; sb < nsb; ++sb) {
        int s0 = sb * 64;
        // load K tile [s][d] and V^T tile [d][s]
#pragma unroll
        for (int i = 0; i < 4; ++i) {
            int c = tid + 128 * i;
            int r = c >> 3, c8 = (c & 7) * 8;
            const size_t rowoff = (size_t)(b * NTOK + s0 + r) * N3;
            *(float4*)&Kh[r][c8] = *(const float4*)(qh + rowoff + NE + h * DH + c8);
            *(float4*)&Kl[r][c8] = *(const float4*)(ql + rowoff + NE + h * DH + c8);
            float4 v4h = *(const float4*)(qh + rowoff + 2 * NE + h * DH + c8);
            float4 v4l = *(const float4*)(ql + rowoff + 2 * NE + h * DH + c8);
            const bf16* eh = (const bf16*)&v4h;
            const bf16* el = (const bf16*)&v4l;
#pragma unroll
            for (int j = 0; j < 8; ++j) { Vh[c8 + j][r] = eh[j]; Vl[c8 + j][r] = el[j]; }
        }
        __syncthreads();

        // S = Q K^T (split 3-MMA)
        float accs[8][4];
#pragma unroll
        for (int i = 0; i < 8; ++i)
#pragma unroll
            for (int j = 0; j < 4; ++j) accs[i][j] = 0.f;
#pragma unroll
        for (int nt = 0; nt < 8; ++nt) {
#pragma unroll
            for (int kf = 0; kf < 4; ++kf) {
                uint32_t kbh[2], kbl[2];
                kbh[0] = *(const uint32_t*)&Kh[nt * 8 + g][kf * 16 + 2 * tg];
                kbh[1] = *(const uint32_t*)&Kh[nt * 8 + g][kf * 16 + 8 + 2 * tg];
                kbl[0] = *(const uint32_t*)&Kl[nt * 8 + g][kf * 16 + 2 * tg];
                kbl[1] = *(const uint32_t*)&Kl[nt * 8 + g][kf * 16 + 8 + 2 * tg];
                MMA16816(accs[nt], qfh[kf], kbh);
                MMA16816(accs[nt], qfh[kf], kbl);
                MMA16816(accs[nt], qfl[kf], kbh);
            }
        }

        // scale + causal mask + online softmax
#pragma unroll
        for (int r = 0; r < 2; ++r) {
            int row = t0 + w * 16 + g + 8 * r;
            float rm = -1e30f;
#pragma unroll
            for (int nt = 0; nt < 8; ++nt) {
#pragma unroll
                for (int j = 0; j < 2; ++j) {
                    int col = s0 + nt * 8 + 2 * tg + j;
                    float v = accs[nt][2 * r + j] * 0.125f;
                    if (col > row) v = -1e30f;
                    accs[nt][2 * r + j] = v;
                    rm = fmaxf(rm, v);
                }
            }
            rm = fmaxf(rm, __shfl_xor_sync(0xFFFFFFFFu, rm, 1));
            rm = fmaxf(rm, __shfl_xor_sync(0xFFFFFFFFu, rm, 2));
            float nm = fmaxf(mr[r], rm);
            float fac = __expf(mr[r] - nm);
            mr[r] = nm;
            float rs = 0.f;
#pragma unroll
            for (int nt = 0; nt < 8; ++nt) {
#pragma unroll
                for (int j = 0; j < 2; ++j) {
                    float p = __expf(accs[nt][2 * r + j] - nm);
                    accs[nt][2 * r + j] = p;
                    rs += p;
                }
            }
            rs += __shfl_xor_sync(0xFFFFFFFFu, rs, 1);
            rs += __shfl_xor_sync(0xFFFFFFFFu, rs, 2);
            lr[r] = lr[r] * fac + rs;
#pragma unroll
            for (int nt = 0; nt < 8; ++nt) {
                acco[nt][2 * r + 0] *= fac;
                acco[nt][2 * r + 1] *= fac;
            }
        }

        // O += P V (split 3-MMA)
#pragma unroll
        for (int kf2 = 0; kf2 < 4; ++kf2) {
            uint32_t pah[4], pal[4];
            float p00 = accs[2 * kf2][0],     p01 = accs[2 * kf2][1];
            float p10 = accs[2 * kf2][2],     p11 = accs[2 * kf2][3];
            float p20 = accs[2 * kf2 + 1][0], p21 = accs[2 * kf2 + 1][1];
            float p30 = accs[2 * kf2 + 1][2], p31 = accs[2 * kf2 + 1][3];
            pah[0] = packbf(p00, p01); pah[1] = packbf(p10, p11);
            pah[2] = packbf(p20, p21); pah[3] = packbf(p30, p31);
            __nv_bfloat162* hp;
            hp = (__nv_bfloat162*)&pah[0];
            pal[0] = packbf(p00 - __bfloat162float(hp->x), p01 - __bfloat162float(hp->y));
            hp = (__nv_bfloat162*)&pah[1];
            pal[1] = packbf(p10 - __bfloat162float(hp->x), p11 - __bfloat162float(hp->y));
            hp = (__nv_bfloat162*)&pah[2];
            pal[2] = packbf(p20 - __bfloat162float(hp->x), p21 - __bfloat162float(hp->y));
            hp = (__nv_bfloat162*)&pah[3];
            pal[3] = packbf(p30 - __bfloat162float(hp->x), p31 - __bfloat162float(hp->y));
#pragma unroll
            for (int nt2 = 0; nt2 < 8; ++nt2) {
                uint32_t vbh[2], vbl[2];
                vbh[0] = *(const uint32_t*)&Vh[nt2 * 8 + g][kf2 * 16 + 2 * tg];
                vbh[1] = *(const uint32_t*)&Vh[nt2 * 8 + g][kf2 * 16 + 8 + 2 * tg];
                vbl[0] = *(const uint32_t*)&Vl[nt2 * 8 + g][kf2 * 16 + 2 * tg];
                vbl[1] = *(const uint32_t*)&Vl[nt2 * 8 + g][kf2 * 16 + 8 + 2 * tg];
                MMA16816(acco[nt2], pah, vbh);
                MMA16816(acco[nt2], pah, vbl);
                MMA16816(acco[nt2], pal, vbh);
            }
        }
        __syncthreads();
    }

    // epilogue: y = O / l, written as hi/lo bf16
#pragma unroll
    for (int r = 0; r < 2; ++r) {
        float inv = 1.0f / lr[r];
        int row = t0 + w * 16 + g + 8 * r;
#pragma unroll
        for (int nt2 = 0; nt2 < 8; ++nt2) {
            float v0 = acco[nt2][2 * r + 0] * inv;
            float v1 = acco[nt2][2 * r + 1] * inv;
            bf16 h0 = __float2bfloat16(v0);
            bf16 h1 = __float2bfloat16(v1);
            size_t idx = (size_t)(b * NTOK + row) * NE + h * DH + nt2 * 8 + 2 * tg;
            __nv_bfloat162 hp; hp.x = h0; hp.y = h1;
            *(uint32_t*)(yh + idx) = *(uint32_t*)&hp;
            *(uint32_t*)(yl + idx) = packbf(v0 - __bfloat162float(h0), v1 - __bfloat162float(h1));
        }
    }
}

// ---------------- loss ------------------------------------------------------------
__global__ void __launch_bounds__(256) loss_rows(const float* __restrict__ logits,
                                                 const int* __restrict__ tgt,
                                                 float* __restrict__ rl) {
    int row = blockIdx.x;
    const float* p = logits + (size_t)row * NV;
    __shared__ float sm[256], ss[256];
    int tid = threadIdx.x;

    float m = -INFINITY, s = 0.f;
    for (int j = tid; j < NV; j += 256) {
        float v = p[j];
        float nm = fmaxf(m, v);
        s = s * expf(m - nm) + expf(v - nm);
        m = nm;
    }
    sm[tid] = m; ss[tid] = s; __syncthreads();
    for (int o = 128; o > 0; o >>= 1) {
        if (tid < o) {
            float m2 = sm[tid + o], s2 = ss[tid + o];
            float M = fmaxf(sm[tid], m2);
            ss[tid] = ss[tid] * expf(sm[tid] - M) + s2 * expf(m2 - M);
            sm[tid] = M;
        }
        __syncthreads();
    }
    if (tid == 0) {
        float lt = p[tgt[row]];
        rl[row] = -(lt - sm[0] - logf(ss[0]));
    }
}

__global__ void __launch_bounds__(256) loss_final(const float* __restrict__ rl,
                                                  float* __restrict__ out) {
    __shared__ float red[256];
    int tid = threadIdx.x;
    float s = 0.f;
    for (int i = tid; i < NM; i += 256) s += rl[i];
    red[tid] = s; __syncthreads();
    for (int o = 128; o > 0; o >>= 1) { if (tid < o) red[tid] += red[tid + o]; __syncthreads(); }
    if (tid == 0) out[0] = red[0] * (1.0f / NM);
}

// ---------------- host orchestration ------------------------------------------------
extern "C" void kernel_launch(void* const* d_in, const int* in_sizes, int n_in,
                              void* d_out, int out_size) {
    const int*   x0    = (const int*)  d_in[0];
    const int*   tgt   = (const int*)  d_in[1];
    const float* wte   = (const float*)d_in[2];
    const float* wpe   = (const float*)d_in[3];
    const float* ln1w  = (const float*)d_in[4];
    const float* ln1b  = (const float*)d_in[5];
    const float* Wqkv  = (const float*)d_in[6];
    const float* Wo    = (const float*)d_in[7];
    const float* ln2w  = (const float*)d_in[8];
    const float* ln2b  = (const float*)d_in[9];
    const float* Wfc   = (const float*)d_in[10];
    const float* Wproj = (const float*)d_in[11];
    const float* lnfw  = (const float*)d_in[12];
    const float* lnfb  = (const float*)d_in[13];

    float *px, *pl, *prl;
    bf16 *pwth, *pwtl, *pwteh, *pwtel, *plnh, *plnl, *pqh, *pql, *pyh, *pyl, *pfh, *pfl;
    cudaGetSymbolAddress((void**)&px,  g_x);
    cudaGetSymbolAddress((void**)&pl,  g_logits);
    cudaGetSymbolAddress((void**)&prl, g_rl);
    cudaGetSymbolAddress((void**)&pwth, g_wth);
    cudaGetSymbolAddress((void**)&pwtl, g_wtl);
    cudaGetSymbolAddress((void**)&pwteh, g_wteh);
    cudaGetSymbolAddress((void**)&pwtel, g_wtel);
    cudaGetSymbolAddress((void**)&plnh, g_lnh);
    cudaGetSymbolAddress((void**)&plnl, g_lnl);
    cudaGetSymbolAddress((void**)&pqh, g_qkvh);
    cudaGetSymbolAddress((void**)&pql, g_qkvl);
    cudaGetSymbolAddress((void**)&pyh, g_yh);
    cudaGetSymbolAddress((void**)&pyl, g_yl);
    cudaGetSymbolAddress((void**)&pfh, g_fch);
    cudaGetSymbolAddress((void**)&pfl, g_fcl);

    // dynamic smem caps for gemm2 variants
    const int SM_WM2 = (2 * 128 * 40 * 2 + 2 * 128 * 40 * 2) * 2;  // 81920 B
    const int SM_WM4 = (2 * 128 * 40 * 2 + 2 * 64  * 40 * 2) * 2;  // 61440 B
    cudaFuncSetAttribute(gemm2<0,1,2>, cudaFuncAttributeMaxDynamicSharedMemorySize, SM_WM2);
    cudaFuncSetAttribute(gemm2<2,1,2>, cudaFuncAttributeMaxDynamicSharedMemorySize, SM_WM2);
    cudaFuncSetAttribute(gemm2<0,0,2>, cudaFuncAttributeMaxDynamicSharedMemorySize, SM_WM2);
    cudaFuncSetAttribute(gemm2<1,0,4>, cudaFuncAttributeMaxDynamicSharedMemorySize, SM_WM4);

    dim3 t32(32, 32);
    // weight transpose+split
    for (int l = 0; l < NL; ++l) {
        size_t off = (size_t)l * LPL;
        tsplit_kernel<<<dim3(N3 / 32, NE / 32), t32>>>(
            Wqkv + (size_t)l * NE * N3, pwth + off, pwtl + off, NE, N3);
        off += LQKV;
        tsplit_kernel<<<dim3(NE / 32, NE / 32), t32>>>(
            Wo + (size_t)l * NE * NE, pwth + off, pwtl + off, NE, NE);
        off += LWO;
        tsplit_kernel<<<dim3(N4 / 32, NE / 32), t32>>>(
            Wfc + (size_t)l * NE * N4, pwth + off, pwtl + off, NE, N4);
        off += LWFC;
        tsplit_kernel<<<dim3(NE / 32, N4 / 32), t32>>>(
            Wproj + (size_t)l * N4 * NE, pwth + off, pwtl + off, N4, NE);
    }
    split_kernel<<<((size_t)NV * NE + 255) / 256, 256>>>(wte, pwteh, pwtel, NV * NE);

    embed_kernel<<<(NM * NE + 255) / 256, 256>>>(x0, wte, wpe, px);

    for (int l = 0; l < NL; ++l) {
        size_t off = (size_t)l * LPL;
        ln_split<<<NM, 256>>>(px, ln1w + (size_t)l * NE, ln1b + (size_t)l * NE, plnh, plnl);
        gemm2<0,1,2><<<dim3(N3 / 128, NM / 128), 256, SM_WM2>>>(
            plnh, plnl, pwth + off, pwtl + off, nullptr, pqh, pql, nullptr, NM, N3, NE);
        flash_kernel<<<dim3(NTOK / 64, NB * NH), 128>>>(pqh, pql, pyh, pyl);
        gemm2<1,0,4><<<dim3(NE / 64, NM / 128), 256, SM_WM4>>>(
            pyh, pyl, pwth + off + LQKV, pwtl + off + LQKV, px, nullptr, nullptr, px, NM, NE, NE);
        ln_split<<<NM, 256>>>(px, ln2w + (size_t)l * NE, ln2b + (size_t)l * NE, plnh, plnl);
        gemm2<2,1,2><<<dim3(N4 / 128, NM / 128), 256, SM_WM2>>>(
            plnh, plnl, pwth + off + LQKV + LWO, pwtl + off + LQKV + LWO,
            nullptr, pfh, pfl, nullptr, NM, N4, NE);
        gemm2<1,0,4><<<dim3(NE / 64, NM / 128), 256, SM_WM4>>>(
            pfh, pfl, pwth + off + LQKV + LWO + LWFC, pwtl + off + LQKV + LWO + LWFC,
            px, nullptr, nullptr, px, NM, NE, N4);
    }

    ln_split<<<NM, 256>>>(px, lnfw, lnfb, plnh, plnl);

    const size_t logits_elems = (size_t)NM * NV;
    float* logits = ((size_t)out_size >= logits_elems) ? (float*)d_out : pl;
    gemm2<0,0,2><<<dim3((NV + 127) / 128, NM / 128), 256, SM_WM2>>>(
        plnh, plnl, pwteh, pwtel, logits, nullptr, nullptr, nullptr, NM, NV, NE);

    loss_rows<<<NM, 256>>>(logits, tgt, prl);
    if ((size_t)out_size > logits_elems) {
        loss_final<<<1, 256>>>(prl, (float*)d_out + logits_elems);
    } else if (logits != (float*)d_out) {
        loss_final<<<1, 256>>>(prl, (float*)d_out);
    }
}

// round 4
// speedup vs baseline: 2.5062x; 1.0587x over previous
#include <cuda_runtime.h>
#include <cuda_bf16.h>
#include <math.h>
#include <stdint.h>

// GPT-2 small fwd: B=2 T=1024 E=768 H=12 L=6 V=50257
#define NB 2
#define NTOK 1024
#define NE 768
#define NH 12
#define DH 64
#define NL 6
#define NV 50257
#define NM (NB*NTOK)
#define N3 (3*NE)
#define N4 (4*NE)

#define LQKV (N3*NE)
#define LWO  (NE*NE)
#define LWFC (N4*NE)
#define LWPR (NE*N4)
#define LPL  (LQKV+LWO+LWFC+LWPR)

#define NTN 393          // ceil(NV/128)
#define NTP (NTN*4)      // per-row partial tiles (4 warps per 128-col tile)

typedef __nv_bfloat16 bf16;

// ---------------- scratch ------------------------------------------------------
static __device__ float g_x  [NM*NE];
static __device__ float g_logits[(size_t)NM*NV];
static __device__ float g_rl [NM];
static __device__ float g_pm [(size_t)NM*NTP];
static __device__ float g_ps [(size_t)NM*NTP];
static __device__ bf16 g_wth[(size_t)NL*LPL];
static __device__ bf16 g_wtl[(size_t)NL*LPL];
static __device__ bf16 g_wteh[(size_t)NV*NE];
static __device__ bf16 g_wtel[(size_t)NV*NE];
static __device__ bf16 g_lnh[NM*NE];
static __device__ bf16 g_lnl[NM*NE];
static __device__ bf16 g_qkvh[NM*N3];
static __device__ bf16 g_qkvl[NM*N3];
static __device__ bf16 g_yh[NM*NE];
static __device__ bf16 g_yl[NM*NE];
static __device__ bf16 g_fch[NM*N4];
static __device__ bf16 g_fcl[NM*N4];

// ---------------- helpers -------------------------------------------------------
__device__ __forceinline__ uint32_t packbf(float a, float b) {
    __nv_bfloat162 t;
    t.x = __float2bfloat16(a);
    t.y = __float2bfloat16(b);
    return *(uint32_t*)&t;
}

__device__ __forceinline__ void cpa16(void* dst, const void* src) {
    uint32_t d = (uint32_t)__cvta_generic_to_shared(dst);
    asm volatile("cp.async.cg.shared.global [%0], [%1], 16;" :: "r"(d), "l"(src));
}
__device__ __forceinline__ void cpa16z(void* dst, const void* src, int sz) {
    uint32_t d = (uint32_t)__cvta_generic_to_shared(dst);
    asm volatile("cp.async.cg.shared.global [%0], [%1], 16, %2;" :: "r"(d), "l"(src), "r"(sz));
}
#define CP_COMMIT() asm volatile("cp.async.commit_group;")
#define CP_WAIT(n)  asm volatile("cp.async.wait_group %0;" :: "n"(n))

#define MMA16816(c, a, b) \
    asm volatile("mma.sync.aligned.m16n8k16.row.col.f32.bf16.bf16.f32 " \
                 "{%0,%1,%2,%3}, {%4,%5,%6,%7}, {%8,%9}, {%0,%1,%2,%3};" \
                 : "+f"((c)[0]), "+f"((c)[1]), "+f"((c)[2]), "+f"((c)[3]) \
                 : "r"((a)[0]), "r"((a)[1]), "r"((a)[2]), "r"((a)[3]), \
                   "r"((b)[0]), "r"((b)[1]))

__device__ __forceinline__ float gelu_tanh(float x) {
    const float c = 0.7978845608028654f;
    float x3 = x * x * x;
    return 0.5f * x * (1.0f + tanhf(c * (x + 0.044715f * x3)));
}

__device__ __forceinline__ void lse_merge(float& m, float& s, float m2, float s2) {
    float M = fmaxf(m, m2);
    if (M == -INFINITY) { m = M; s = 0.f; return; }
    float e1 = (m  == -INFINITY) ? 0.f : expf(m  - M);
    float e2 = (m2 == -INFINITY) ? 0.f : expf(m2 - M);
    s = s * e1 + s2 * e2;
    m = M;
}

// ---------------- embed ---------------------------------------------------------
__global__ void embed_kernel(const int* __restrict__ x0,
                             const float* __restrict__ wte,
                             const float* __restrict__ wpe,
                             float* __restrict__ x) {
    int i = blockIdx.x * blockDim.x + threadIdx.x;
    if (i >= NM * NE) return;
    int tok = i / NE, e = i - tok * NE;
    int t = tok % NTOK;
    int id = x0[tok];
    x[i] = wte[(size_t)id * NE + e] + wpe[(size_t)t * NE + e];
}

// ---------------- layernorm -> split bf16 (warp per token) -----------------------
__global__ void __launch_bounds__(256) ln_split2(const float* __restrict__ x,
                                                 const float* __restrict__ w,
                                                 const float* __restrict__ b,
                                                 bf16* __restrict__ oh,
                                                 bf16* __restrict__ ol) {
    int warp = threadIdx.x >> 5, lane = threadIdx.x & 31;
    int tok = blockIdx.x * 8 + warp;
    const float* row = x + (size_t)tok * NE;

    float v[24];
    float s = 0.f;
#pragma unroll
    for (int j = 0; j < 6; ++j) {
        float4 f = *(const float4*)(row + j * 128 + lane * 4);
        v[4*j] = f.x; v[4*j+1] = f.y; v[4*j+2] = f.z; v[4*j+3] = f.w;
        s += (f.x + f.y) + (f.z + f.w);
    }
#pragma unroll
    for (int o = 16; o > 0; o >>= 1) s += __shfl_xor_sync(0xFFFFFFFFu, s, o);
    float mean = s * (1.0f / NE);

    float var = 0.f;
#pragma unroll
    for (int i = 0; i < 24; ++i) { float d = v[i] - mean; var += d * d; }
#pragma unroll
    for (int o = 16; o > 0; o >>= 1) var += __shfl_xor_sync(0xFFFFFFFFu, var, o);
    float rstd = rsqrtf(var * (1.0f / NE) + 1e-6f);

#pragma unroll
    for (int j = 0; j < 6; ++j) {
        float4 w4 = *(const float4*)(w + j * 128 + lane * 4);
        float4 b4 = *(const float4*)(b + j * 128 + lane * 4);
        float o0 = (v[4*j]   - mean) * rstd * w4.x + b4.x;
        float o1 = (v[4*j+1] - mean) * rstd * w4.y + b4.y;
        float o2 = (v[4*j+2] - mean) * rstd * w4.z + b4.z;
        float o3 = (v[4*j+3] - mean) * rstd * w4.w + b4.w;
        bf16 h0 = __float2bfloat16(o0), h1 = __float2bfloat16(o1);
        bf16 h2 = __float2bfloat16(o2), h3 = __float2bfloat16(o3);
        uint2 H, L;
        { __nv_bfloat162 p; p.x = h0; p.y = h1; H.x = *(uint32_t*)&p;
          p.x = h2; p.y = h3; H.y = *(uint32_t*)&p; }
        L.x = packbf(o0 - __bfloat162float(h0), o1 - __bfloat162float(h1));
        L.y = packbf(o2 - __bfloat162float(h2), o3 - __bfloat162float(h3));
        *(uint2*)(oh + (size_t)tok * NE + j * 128 + lane * 4) = H;
        *(uint2*)(ol + (size_t)tok * NE + j * 128 + lane * 4) = L;
    }
}

// ---------------- vectorized split (wte) ------------------------------------------
__global__ void split4(const float* __restrict__ x,
                       bf16* __restrict__ hi, bf16* __restrict__ lo, int n4) {
    int i = blockIdx.x * blockDim.x + threadIdx.x;
    if (i >= n4) return;
    float4 v = ((const float4*)x)[i];
    bf16 h0 = __float2bfloat16(v.x), h1 = __float2bfloat16(v.y);
    bf16 h2 = __float2bfloat16(v.z), h3 = __float2bfloat16(v.w);
    uint2 H, L;
    { __nv_bfloat162 p; p.x = h0; p.y = h1; H.x = *(uint32_t*)&p;
      p.x = h2; p.y = h3; H.y = *(uint32_t*)&p; }
    L.x = packbf(v.x - __bfloat162float(h0), v.y - __bfloat162float(h1));
    L.y = packbf(v.z - __bfloat162float(h2), v.w - __bfloat162float(h3));
    ((uint2*)hi)[i] = H;
    ((uint2*)lo)[i] = L;
}

// ---------------- vectorized transpose-split: in[K,N] -> out[N,K] -----------------
// grid (N/64, K/32), 256 threads. All dims are multiples (768/2304/3072).
__global__ void __launch_bounds__(256) tsplit2(const float* __restrict__ in,
                                               bf16* __restrict__ oh,
                                               bf16* __restrict__ ol,
                                               int K, int N) {
    __shared__ float t[32][65];
    int tid = threadIdx.x;
    int kb = blockIdx.y * 32, nb = blockIdx.x * 64;
#pragma unroll
    for (int i = 0; i < 2; ++i) {
        int id = tid + 256 * i;
        int r = id >> 4, c4 = (id & 15) * 4;
        float4 v = *(const float4*)(in + (size_t)(kb + r) * N + nb + c4);
        t[r][c4] = v.x; t[r][c4+1] = v.y; t[r][c4+2] = v.z; t[r][c4+3] = v.w;
    }
    __syncthreads();
#pragma unroll
    for (int i = 0; i < 4; ++i) {
        int id = tid + 256 * i;
        int n = id >> 4, kp = id & 15;
        float v0 = t[2*kp][n], v1 = t[2*kp+1][n];
        bf16 h0 = __float2bfloat16(v0), h1 = __float2bfloat16(v1);
        uint32_t H;
        { __nv_bfloat162 p; p.x = h0; p.y = h1; H = *(uint32_t*)&p; }
        uint32_t L = packbf(v0 - __bfloat162float(h0), v1 - __bfloat162float(h1));
        size_t idx = (size_t)(nb + n) * K + kb + 2 * kp;
        *(uint32_t*)(oh + idx) = H;
        *(uint32_t*)(ol + idx) = L;
    }
}

// ---------------- GEMM: double-buffered cp.async split-bf16 HMMA, occ 2 ------------
// C = epi(A[M,K] * B^T), B stored [N,K].
// EPI: 0 none, 1 +R, 2 gelu, 3 fp32 out + logsumexp partials (PM/PS).
// OUT: 0 fp32 C, 1 bf16 hi/lo pair. WM: warps in M (2 -> BN=128, 4 -> BN=64).
template<int EPI, int OUT, int WM>
__global__ void __launch_bounds__(256, 2) gemm2(
    const bf16* __restrict__ Ah, const bf16* __restrict__ Al,
    const bf16* __restrict__ Bh, const bf16* __restrict__ Bl,
    float* __restrict__ C, bf16* __restrict__ Ch, bf16* __restrict__ Cl,
    const float* __restrict__ R, float* __restrict__ PM, float* __restrict__ PS,
    int M, int N, int K)
{
    constexpr int WN = 8 / WM;
    constexpr int BN = WN * 32;
    constexpr int MT = 128 / (16 * WM);
    extern __shared__ bf16 smem[];
    bf16* Ash = smem;
    bf16* Asl = Ash + 2 * 128 * 40;
    bf16* Bsh = Asl + 2 * 128 * 40;
    bf16* Bsl = Bsh + 2 * BN * 40;

    const int tid = threadIdx.x;
    const int lane = tid & 31, wid = tid >> 5;
    const int wm = wid / WN, wn = wid % WN;
    const int g = lane >> 2, tg = lane & 3;
    const int m0 = blockIdx.y * 128;
    const int n0 = blockIdx.x * BN;

    float acc[MT][4][4];
#pragma unroll
    for (int a = 0; a < MT; ++a)
#pragma unroll
        for (int b = 0; b < 4; ++b)
#pragma unroll
            for (int c = 0; c < 4; ++c) acc[a][b][c] = 0.f;

    auto load_stage = [&](int st, int k0) {
#pragma unroll
        for (int i = 0; i < 2; ++i) {
            int c = tid + 256 * i;
            int r = c >> 2, cq = (c & 3) * 8;
            cpa16(&Ash[(st * 128 + r) * 40 + cq], Ah + (size_t)(m0 + r) * K + k0 + cq);
            cpa16(&Asl[(st * 128 + r) * 40 + cq], Al + (size_t)(m0 + r) * K + k0 + cq);
        }
        for (int c = tid; c < BN * 4; c += 256) {
            int r = c >> 2, cq = (c & 3) * 8;
            int n = n0 + r;
            int ok = n < N;
            size_t src = (size_t)(ok ? n : 0) * K + k0 + cq;
            cpa16z(&Bsh[(st * BN + r) * 40 + cq], Bh + src, ok ? 16 : 0);
            cpa16z(&Bsl[(st * BN + r) * 40 + cq], Bl + src, ok ? 16 : 0);
        }
    };

    load_stage(0, 0);
    CP_COMMIT();
    const int nk = K / 32;
    for (int it = 0; it < nk; ++it) {
        int st = it & 1;
        if (it + 1 < nk) { load_stage(st ^ 1, (it + 1) * 32); CP_COMMIT(); CP_WAIT(1); }
        else            { CP_WAIT(0); }
        __syncthreads();
#pragma unroll
        for (int kk = 0; kk < 32; kk += 16) {
            uint32_t bhf[4][2], blf[4][2];
#pragma unroll
            for (int nt = 0; nt < 4; ++nt) {
                int cb = st * BN + wn * 32 + nt * 8;
                bhf[nt][0] = *(const uint32_t*)&Bsh[(cb + g) * 40 + kk + 2 * tg];
                bhf[nt][1] = *(const uint32_t*)&Bsh[(cb + g) * 40 + kk + 8 + 2 * tg];
                blf[nt][0] = *(const uint32_t*)&Bsl[(cb + g) * 40 + kk + 2 * tg];
                blf[nt][1] = *(const uint32_t*)&Bsl[(cb + g) * 40 + kk + 8 + 2 * tg];
            }
            // process m-frags in halves of 2 to bound register pressure (occ 2)
#pragma unroll
            for (int mh = 0; mh < MT; mh += 2) {
                uint32_t ah[2][4], al[2][4];
#pragma unroll
                for (int q = 0; q < 2 && mh + q < MT; ++q) {
                    int rb = st * 128 + wm * MT * 16 + (mh + q) * 16;
                    ah[q][0] = *(const uint32_t*)&Ash[(rb + g    ) * 40 + kk + 2 * tg];
                    ah[q][1] = *(const uint32_t*)&Ash[(rb + g + 8) * 40 + kk + 2 * tg];
                    ah[q][2] = *(const uint32_t*)&Ash[(rb + g    ) * 40 + kk + 8 + 2 * tg];
                    ah[q][3] = *(const uint32_t*)&Ash[(rb + g + 8) * 40 + kk + 8 + 2 * tg];
                    al[q][0] = *(const uint32_t*)&Asl[(rb + g    ) * 40 + kk + 2 * tg];
                    al[q][1] = *(const uint32_t*)&Asl[(rb + g + 8) * 40 + kk + 2 * tg];
                    al[q][2] = *(const uint32_t*)&Asl[(rb + g    ) * 40 + kk + 8 + 2 * tg];
                    al[q][3] = *(const uint32_t*)&Asl[(rb + g + 8) * 40 + kk + 8 + 2 * tg];
                }
#pragma unroll
                for (int q = 0; q < 2 && mh + q < MT; ++q)
#pragma unroll
                    for (int nt = 0; nt < 4; ++nt) {
                        MMA16816(acc[mh + q][nt], ah[q], bhf[nt]);
                        MMA16816(acc[mh + q][nt], ah[q], blf[nt]);
                        MMA16816(acc[mh + q][nt], al[q], bhf[nt]);
                    }
            }
        }
        __syncthreads();
    }

    if (EPI == 3) {
        // fp32 store + per-(row, warp-tile) logsumexp partials
        int tile = blockIdx.x * WN + wn;
#pragma unroll
        for (int mt = 0; mt < MT; ++mt) {
#pragma unroll
            for (int r = 0; r < 2; ++r) {
                int m = m0 + wm * MT * 16 + mt * 16 + g + 8 * r;
                float vals[8];
                float rm = -INFINITY;
#pragma unroll
                for (int nt = 0; nt < 4; ++nt)
#pragma unroll
                    for (int j = 0; j < 2; ++j) {
                        int n = n0 + wn * 32 + nt * 8 + 2 * tg + j;
                        float v = acc[mt][nt][2 * r + j];
                        if (n < N) {
                            C[(size_t)m * N + n] = v;
                            rm = fmaxf(rm, v);
                            vals[nt * 2 + j] = v;
                        } else {
                            vals[nt * 2 + j] = -INFINITY;
                        }
                    }
                rm = fmaxf(rm, __shfl_xor_sync(0xFFFFFFFFu, rm, 1));
                rm = fmaxf(rm, __shfl_xor_sync(0xFFFFFFFFu, rm, 2));
                float s = 0.f;
                if (rm != -INFINITY) {
#pragma unroll
                    for (int i = 0; i < 8; ++i)
                        s += (vals[i] == -INFINITY) ? 0.f : expf(vals[i] - rm);
                }
                s += __shfl_xor_sync(0xFFFFFFFFu, s, 1);
                s += __shfl_xor_sync(0xFFFFFFFFu, s, 2);
                if (tg == 0) {
                    PM[(size_t)m * NTP + tile] = rm;
                    PS[(size_t)m * NTP + tile] = s;
                }
            }
        }
        return;
    }

#pragma unroll
    for (int mt = 0; mt < MT; ++mt) {
#pragma unroll
        for (int nt = 0; nt < 4; ++nt) {
            int nbase = n0 + wn * 32 + nt * 8 + 2 * tg;
#pragma unroll
            for (int r = 0; r < 2; ++r) {
                int m = m0 + wm * MT * 16 + mt * 16 + g + 8 * r;
                float v0 = acc[mt][nt][2 * r + 0];
                float v1 = acc[mt][nt][2 * r + 1];
                if (EPI == 1) {
                    if (nbase     < N) v0 += R[(size_t)m * N + nbase];
                    if (nbase + 1 < N) v1 += R[(size_t)m * N + nbase + 1];
                }
                if (EPI == 2) { v0 = gelu_tanh(v0); v1 = gelu_tanh(v1); }
                if (OUT == 0) {
                    if (nbase     < N) C[(size_t)m * N + nbase]     = v0;
                    if (nbase + 1 < N) C[(size_t)m * N + nbase + 1] = v1;
                } else {
                    bf16 h0 = __float2bfloat16(v0);
                    bf16 h1 = __float2bfloat16(v1);
                    float l0 = v0 - __bfloat162float(h0);
                    float l1 = v1 - __bfloat162float(h1);
                    __nv_bfloat162 hp; hp.x = h0; hp.y = h1;
                    *(uint32_t*)(Ch + (size_t)m * N + nbase) = *(uint32_t*)&hp;
                    *(uint32_t*)(Cl + (size_t)m * N + nbase) = packbf(l0, l1);
                }
            }
        }
    }
}

// ---------------- flash attention (split-bf16 MMA, causal, online softmax) --------
#define FP 72
__global__ void __launch_bounds__(128) flash_kernel(
    const bf16* __restrict__ qh, const bf16* __restrict__ ql,
    bf16* __restrict__ yh, bf16* __restrict__ yl)
{
    __shared__ bf16 Kh[64][FP], Kl[64][FP], Vh[64][FP], Vl[64][FP];
    const int bh = blockIdx.y, b = bh / NH, h = bh % NH;
    const int t0 = blockIdx.x * 64;
    const int tid = threadIdx.x, lane = tid & 31, w = tid >> 5;
    const int g = lane >> 2, tg = lane & 3;

#pragma unroll
    for (int i = 0; i < 4; ++i) {
        int c = tid + 128 * i;
        int r = c >> 3, c8 = (c & 7) * 8;
        *(float4*)&Kh[r][c8] = *(const float4*)(qh + (size_t)(b * NTOK + t0 + r) * N3 + h * DH + c8);
        *(float4*)&Kl[r][c8] = *(const float4*)(ql + (size_t)(b * NTOK + t0 + r) * N3 + h * DH + c8);
    }
    __syncthreads();
    uint32_t qfh[4][4], qfl[4][4];
    {
        int rb = w * 16;
#pragma unroll
        for (int kf = 0; kf < 4; ++kf) {
            qfh[kf][0] = *(const uint32_t*)&Kh[rb + g    ][kf * 16 + 2 * tg];
            qfh[kf][1] = *(const uint32_t*)&Kh[rb + g + 8][kf * 16 + 2 * tg];
            qfh[kf][2] = *(const uint32_t*)&Kh[rb + g    ][kf * 16 + 8 + 2 * tg];
            qfh[kf][3] = *(const uint32_t*)&Kh[rb + g + 8][kf * 16 + 8 + 2 * tg];
            qfl[kf][0] = *(const uint32_t*)&Kl[rb + g    ][kf * 16 + 2 * tg];
            qfl[kf][1] = *(const uint32_t*)&Kl[rb + g + 8][kf * 16 + 2 * tg];
            qfl[kf][2] = *(const uint32_t*)&Kl[rb + g    ][kf * 16 + 8 + 2 * tg];
            qfl[kf][3] = *(const uint32_t*)&Kl[rb + g + 8][kf * 16 + 8 + 2 * tg];
        }
    }
    __syncthreads();

    float mr[2] = {-1e30f, -1e30f};
    float lr[2] = {0.f, 0.f};
    float acco[8][4];
#pragma unroll
    for (int i = 0; i < 8; ++i)
#pragma unroll
        for (int j = 0; j < 4; ++j) acco[i][j] = 0.f;

    const int nsb = blockIdx.x + 1;
    for (int sb = 0; sb < nsb; ++sb) {
        int s0 = sb * 64;
#pragma unroll
        for (int i = 0; i < 4; ++i) {
            int c = tid + 128 * i;
            int r = c >> 3, c8 = (c & 7) * 8;
            const size_t rowoff = (size_t)(b * NTOK + s0 + r) * N3;
            *(float4*)&Kh[r][c8] = *(const float4*)(qh + rowoff + NE + h * DH + c8);
            *(float4*)&Kl[r][c8] = *(const float4*)(ql + rowoff + NE + h * DH + c8);
            float4 v4h = *(const float4*)(qh + rowoff + 2 * NE + h * DH + c8);
            float4 v4l = *(const float4*)(ql + rowoff + 2 * NE + h * DH + c8);
            const bf16* eh = (const bf16*)&v4h;
            const bf16* el = (const bf16*)&v4l;
#pragma unroll
            for (int j = 0; j < 8; ++j) { Vh[c8 + j][r] = eh[j]; Vl[c8 + j][r] = el[j]; }
        }
        __syncthreads();

        float accs[8][4];
#pragma unroll
        for (int i = 0; i < 8; ++i)
#pragma unroll
            for (int j = 0; j < 4; ++j) accs[i][j] = 0.f;
#pragma unroll
        for (int nt = 0; nt < 8; ++nt) {
#pragma unroll
            for (int kf = 0; kf < 4; ++kf) {
                uint32_t kbh[2], kbl[2];
                kbh[0] = *(const uint32_t*)&Kh[nt * 8 + g][kf * 16 + 2 * tg];
                kbh[1] = *(const uint32_t*)&Kh[nt * 8 + g][kf * 16 + 8 + 2 * tg];
                kbl[0] = *(const uint32_t*)&Kl[nt * 8 + g][kf * 16 + 2 * tg];
                kbl[1] = *(const uint32_t*)&Kl[nt * 8 + g][kf * 16 + 8 + 2 * tg];
                MMA16816(accs[nt], qfh[kf], kbh);
                MMA16816(accs[nt], qfh[kf], kbl);
                MMA16816(accs[nt], qfl[kf], kbh);
            }
        }

#pragma unroll
        for (int r = 0; r < 2; ++r) {
            int row = t0 + w * 16 + g + 8 * r;
            float rm = -1e30f;
#pragma unroll
            for (int nt = 0; nt < 8; ++nt) {
#pragma unroll
                for (int j = 0; j < 2; ++j) {
                    int col = s0 + nt * 8 + 2 * tg + j;
                    float v = accs[nt][2 * r + j] * 0.125f;
                    if (col > row) v = -1e30f;
                    accs[nt][2 * r + j] = v;
                    rm = fmaxf(rm, v);
                }
            }
            rm = fmaxf(rm, __shfl_xor_sync(0xFFFFFFFFu, rm, 1));
            rm = fmaxf(rm, __shfl_xor_sync(0xFFFFFFFFu, rm, 2));
            float nm = fmaxf(mr[r], rm);
            float fac = __expf(mr[r] - nm);
            mr[r] = nm;
            float rs = 0.f;
#pragma unroll
            for (int nt = 0; nt < 8; ++nt) {
#pragma unroll
                for (int j = 0; j < 2; ++j) {
                    float p = __expf(accs[nt][2 * r + j] - nm);
                    accs[nt][2 * r + j] = p;
                    rs += p;
                }
            }
            rs += __shfl_xor_sync(0xFFFFFFFFu, rs, 1);
            rs += __shfl_xor_sync(0xFFFFFFFFu, rs, 2);
            lr[r] = lr[r] * fac + rs;
#pragma unroll
            for (int nt = 0; nt < 8; ++nt) {
                acco[nt][2 * r + 0] *= fac;
                acco[nt][2 * r + 1] *= fac;
            }
        }

#pragma unroll
        for (int kf2 = 0; kf2 < 4; ++kf2) {
            uint32_t pah[4], pal[4];
            float p00 = accs[2 * kf2][0],     p01 = accs[2 * kf2][1];
            float p10 = accs[2 * kf2][2],     p11 = accs[2 * kf2][3];
            float p20 = accs[2 * kf2 + 1][0], p21 = accs[2 * kf2 + 1][1];
            float p30 = accs[2 * kf2 + 1][2], p31 = accs[2 * kf2 + 1][3];
            pah[0] = packbf(p00, p01); pah[1] = packbf(p10, p11);
            pah[2] = packbf(p20, p21); pah[3] = packbf(p30, p31);
            __nv_bfloat162* hp;
            hp = (__nv_bfloat162*)&pah[0];
            pal[0] = packbf(p00 - __bfloat162float(hp->x), p01 - __bfloat162float(hp->y));
            hp = (__nv_bfloat162*)&pah[1];
            pal[1] = packbf(p10 - __bfloat162float(hp->x), p11 - __bfloat162float(hp->y));
            hp = (__nv_bfloat162*)&pah[2];
            pal[2] = packbf(p20 - __bfloat162float(hp->x), p21 - __bfloat162float(hp->y));
            hp = (__nv_bfloat162*)&pah[3];
            pal[3] = packbf(p30 - __bfloat162float(hp->x), p31 - __bfloat162float(hp->y));
#pragma unroll
            for (int nt2 = 0; nt2 < 8; ++nt2) {
                uint32_t vbh[2], vbl[2];
                vbh[0] = *(const uint32_t*)&Vh[nt2 * 8 + g][kf2 * 16 + 2 * tg];
                vbh[1] = *(const uint32_t*)&Vh[nt2 * 8 + g][kf2 * 16 + 8 + 2 * tg];
                vbl[0] = *(const uint32_t*)&Vl[nt2 * 8 + g][kf2 * 16 + 2 * tg];
                vbl[1] = *(const uint32_t*)&Vl[nt2 * 8 + g][kf2 * 16 + 8 + 2 * tg];
                MMA16816(acco[nt2], pah, vbh);
                MMA16816(acco[nt2], pah, vbl);
                MMA16816(acco[nt2], pal, vbh);
            }
        }
        __syncthreads();
    }

#pragma unroll
    for (int r = 0; r < 2; ++r) {
        float inv = 1.0f / lr[r];
        int row = t0 + w * 16 + g + 8 * r;
#pragma unroll
        for (int nt2 = 0; nt2 < 8; ++nt2) {
            float v0 = acco[nt2][2 * r + 0] * inv;
            float v1 = acco[nt2][2 * r + 1] * inv;
            bf16 h0 = __float2bfloat16(v0);
            bf16 h1 = __float2bfloat16(v1);
            size_t idx = (size_t)(b * NTOK + row) * NE + h * DH + nt2 * 8 + 2 * tg;
            __nv_bfloat162 hp; hp.x = h0; hp.y = h1;
            *(uint32_t*)(yh + idx) = *(uint32_t*)&hp;
            *(uint32_t*)(yl + idx) = packbf(v0 - __bfloat162float(h0), v1 - __bfloat162float(h1));
        }
    }
}

// ---------------- loss: merge logsumexp partials ----------------------------------
__global__ void __launch_bounds__(256) loss_rows2(const float* __restrict__ pm,
                                                  const float* __restrict__ ps,
                                                  const float* __restrict__ logits,
                                                  const int* __restrict__ tgt,
                                                  float* __restrict__ rl) {
    int row = blockIdx.x;
    int tid = threadIdx.x;
    __shared__ float sm[256], ss[256];

    float m = -INFINITY, s = 0.f;
    for (int i = tid; i < NTP; i += 256)
        lse_merge(m, s, pm[(size_t)row * NTP + i], ps[(size_t)row * NTP + i]);
    sm[tid] = m; ss[tid] = s; __syncthreads();
    for (int o = 128; o > 0; o >>= 1) {
        if (tid < o) {
            float mm = sm[tid], sv = ss[tid];
            lse_merge(mm, sv, sm[tid + o], ss[tid + o]);
            sm[tid] = mm; ss[tid] = sv;
        }
        __syncthreads();
    }
    if (tid == 0) {
        float lt = logits[(size_t)row * NV + tgt[row]];
        rl[row] = -(lt - sm[0] - logf(ss[0]));
    }
}

__global__ void __launch_bounds__(256) loss_final(const float* __restrict__ rl,
                                                  float* __restrict__ out) {
    __shared__ float red[256];
    int tid = threadIdx.x;
    float s = 0.f;
    for (int i = tid; i < NM; i += 256) s += rl[i];
    red[tid] = s; __syncthreads();
    for (int o = 128; o > 0; o >>= 1) { if (tid < o) red[tid] += red[tid + o]; __syncthreads(); }
    if (tid == 0) out[0] = red[0] * (1.0f / NM);
}

// ---------------- host orchestration ------------------------------------------------
extern "C" void kernel_launch(void* const* d_in, const int* in_sizes, int n_in,
                              void* d_out, int out_size) {
    const int*   x0    = (const int*)  d_in[0];
    const int*   tgt   = (const int*)  d_in[1];
    const float* wte   = (const float*)d_in[2];
    const float* wpe   = (const float*)d_in[3];
    const float* ln1w  = (const float*)d_in[4];
    const float* ln1b  = (const float*)d_in[5];
    const float* Wqkv  = (const float*)d_in[6];
    const float* Wo    = (const float*)d_in[7];
    const float* ln2w  = (const float*)d_in[8];
    const float* ln2b  = (const float*)d_in[9];
    const float* Wfc   = (const float*)d_in[10];
    const float* Wproj = (const float*)d_in[11];
    const float* lnfw  = (const float*)d_in[12];
    const float* lnfb  = (const float*)d_in[13];

    float *px, *pl, *prl, *ppm, *pps;
    bf16 *pwth, *pwtl, *pwteh, *pwtel, *plnh, *plnl, *pqh, *pql, *pyh, *pyl, *pfh, *pfl;
    cudaGetSymbolAddress((void**)&px,  g_x);
    cudaGetSymbolAddress((void**)&pl,  g_logits);
    cudaGetSymbolAddress((void**)&prl, g_rl);
    cudaGetSymbolAddress((void**)&ppm, g_pm);
    cudaGetSymbolAddress((void**)&pps, g_ps);
    cudaGetSymbolAddress((void**)&pwth, g_wth);
    cudaGetSymbolAddress((void**)&pwtl, g_wtl);
    cudaGetSymbolAddress((void**)&pwteh, g_wteh);
    cudaGetSymbolAddress((void**)&pwtel, g_wtel);
    cudaGetSymbolAddress((void**)&plnh, g_lnh);
    cudaGetSymbolAddress((void**)&plnl, g_lnl);
    cudaGetSymbolAddress((void**)&pqh, g_qkvh);
    cudaGetSymbolAddress((void**)&pql, g_qkvl);
    cudaGetSymbolAddress((void**)&pyh, g_yh);
    cudaGetSymbolAddress((void**)&pyl, g_yl);
    cudaGetSymbolAddress((void**)&pfh, g_fch);
    cudaGetSymbolAddress((void**)&pfl, g_fcl);

    const int SM_WM2 = (2 * 128 * 40 * 2 + 2 * 128 * 40 * 2) * 2;  // 81920 B
    const int SM_WM4 = (2 * 128 * 40 * 2 + 2 * 64  * 40 * 2) * 2;  // 61440 B
    cudaFuncSetAttribute(gemm2<0,1,2>, cudaFuncAttributeMaxDynamicSharedMemorySize, SM_WM2);
    cudaFuncSetAttribute(gemm2<2,1,2>, cudaFuncAttributeMaxDynamicSharedMemorySize, SM_WM2);
    cudaFuncSetAttribute(gemm2<3,0,2>, cudaFuncAttributeMaxDynamicSharedMemorySize, SM_WM2);
    cudaFuncSetAttribute(gemm2<1,0,4>, cudaFuncAttributeMaxDynamicSharedMemorySize, SM_WM4);

    // weight transpose+split (vectorized)
    for (int l = 0; l < NL; ++l) {
        size_t off = (size_t)l * LPL;
        tsplit2<<<dim3(N3 / 64, NE / 32), 256>>>(
            Wqkv + (size_t)l * NE * N3, pwth + off, pwtl + off, NE, N3);
        off += LQKV;
        tsplit2<<<dim3(NE / 64, NE / 32), 256>>>(
            Wo + (size_t)l * NE * NE, pwth + off, pwtl + off, NE, NE);
        off += LWO;
        tsplit2<<<dim3(N4 / 64, NE / 32), 256>>>(
            Wfc + (size_t)l * NE * N4, pwth + off, pwtl + off, NE, N4);
        off += LWFC;
        tsplit2<<<dim3(NE / 64, N4 / 32), 256>>>(
            Wproj + (size_t)l * N4 * NE, pwth + off, pwtl + off, N4, NE);
    }
    {
        int n4 = (NV * NE) / 4;
        split4<<<(n4 + 255) / 256, 256>>>(wte, pwteh, pwtel, n4);
    }

    embed_kernel<<<(NM * NE + 255) / 256, 256>>>(x0, wte, wpe, px);

    for (int l = 0; l < NL; ++l) {
        size_t off = (size_t)l * LPL;
        ln_split2<<<NM / 8, 256>>>(px, ln1w + (size_t)l * NE, ln1b + (size_t)l * NE, plnh, plnl);
        gemm2<0,1,2><<<dim3(N3 / 128, NM / 128), 256, SM_WM2>>>(
            plnh, plnl, pwth + off, pwtl + off, nullptr, pqh, pql, nullptr,
            nullptr, nullptr, NM, N3, NE);
        flash_kernel<<<dim3(NTOK / 64, NB * NH), 128>>>(pqh, pql, pyh, pyl);
        gemm2<1,0,4><<<dim3(NE / 64, NM / 128), 256, SM_WM4>>>(
            pyh, pyl, pwth + off + LQKV, pwtl + off + LQKV, px, nullptr, nullptr, px,
            nullptr, nullptr, NM, NE, NE);
        ln_split2<<<NM / 8, 256>>>(px, ln2w + (size_t)l * NE, ln2b + (size_t)l * NE, plnh, plnl);
        gemm2<2,1,2><<<dim3(N4 / 128, NM / 128), 256, SM_WM2>>>(
            plnh, plnl, pwth + off + LQKV + LWO, pwtl + off + LQKV + LWO,
            nullptr, pfh, pfl, nullptr, nullptr, nullptr, NM, N4, NE);
        gemm2<1,0,4><<<dim3(NE / 64, NM / 128), 256, SM_WM4>>>(
            pfh, pfl, pwth + off + LQKV + LWO + LWFC, pwtl + off + LQKV + LWO + LWFC,
            px, nullptr, nullptr, px, nullptr, nullptr, NM, NE, N4);
    }

    ln_split2<<<NM / 8, 256>>>(px, lnfw, lnfb, plnh, plnl);

    const size_t logits_elems = (size_t)NM * NV;
    float* logits = ((size_t)out_size >= logits_elems) ? (float*)d_out : pl;
    gemm2<3,0,2><<<dim3(NTN, NM / 128), 256, SM_WM2>>>(
        plnh, plnl, pwteh, pwtel, logits, nullptr, nullptr, nullptr,
        ppm, pps, NM, NV, NE);

    loss_rows2<<<NM, 256>>>(ppm, pps, logits, tgt, prl);
    if ((size_t)out_size > logits_elems) {
        loss_final<<<1, 256>>>(prl, (float*)d_out + logits_elems);
    } else if (logits != (float*)d_out) {
        loss_final<<<1, 256>>>(prl, (float*)d_out);
    }
}

// round 6
// speedup vs baseline: 2.5646x; 1.0233x over previous
#include <cuda_runtime.h>
#include <cuda_bf16.h>
#include <math.h>
#include <stdint.h>

// GPT-2 small fwd: B=2 T=1024 E=768 H=12 L=6 V=50257
#define NB 2
#define NTOK 1024
#define NE 768
#define NH 12
#define DH 64
#define NL 6
#define NV 50257
#define NM (NB*NTOK)
#define N3 (3*NE)
#define N4 (4*NE)

#define LQKV (N3*NE)
#define LWO  (NE*NE)
#define LWFC (N4*NE)
#define LWPR (NE*N4)
#define LPL  (LQKV+LWO+LWFC+LWPR)

#define NTN 393          // ceil(NV/128)
#define NTP (NTN*4)      // per-row lse partial tiles (4 warps per 128-col tile)

typedef __nv_bfloat16 bf16;

// ---------------- scratch ------------------------------------------------------
static __device__ float g_x  [NM*NE];
static __device__ float g_logits[(size_t)NM*NV];
static __device__ float g_rl [NM];
static __device__ float g_pm [(size_t)NM*NTP];
static __device__ float g_ps [(size_t)NM*NTP];
static __device__ bf16 g_wth[(size_t)NL*LPL];
static __device__ bf16 g_wtl[(size_t)NL*LPL];
static __device__ bf16 g_wteh[(size_t)NV*NE];
static __device__ bf16 g_wtel[(size_t)NV*NE];
static __device__ bf16 g_lnh[NM*NE];
static __device__ bf16 g_lnl[NM*NE];
static __device__ bf16 g_qkvh[NM*N3];
static __device__ bf16 g_qkvl[NM*N3];
static __device__ bf16 g_yh[NM*NE];
static __device__ bf16 g_yl[NM*NE];
static __device__ bf16 g_fch[NM*N4];
static __device__ bf16 g_fcl[NM*N4];

// ---------------- helpers -------------------------------------------------------
__device__ __forceinline__ uint32_t packbf(float a, float b) {
    __nv_bfloat162 t;
    t.x = __float2bfloat16(a);
    t.y = __float2bfloat16(b);
    return *(uint32_t*)&t;
}
__device__ __forceinline__ uint32_t smem_u32(const void* p) {
    uint32_t a;
    asm("{ .reg .u64 t; cvta.to.shared.u64 t, %1; cvt.u32.u64 %0, t; }" : "=r"(a) : "l"(p));
    return a;
}
__device__ __forceinline__ void cpa16(void* dst, const void* src) {
    uint32_t d = (uint32_t)__cvta_generic_to_shared(dst);
    asm volatile("cp.async.cg.shared.global [%0], [%1], 16;" :: "r"(d), "l"(src));
}
__device__ __forceinline__ void cpa16z(void* dst, const void* src, int sz) {
    uint32_t d = (uint32_t)__cvta_generic_to_shared(dst);
    asm volatile("cp.async.cg.shared.global [%0], [%1], 16, %2;" :: "r"(d), "l"(src), "r"(sz));
}
#define CP_COMMIT() asm volatile("cp.async.commit_group;")
#define CP_WAIT(n)  asm volatile("cp.async.wait_group %0;" :: "n"(n))

#define MMA16816(c, a, b) \
    asm volatile("mma.sync.aligned.m16n8k16.row.col.f32.bf16.bf16.f32 " \
                 "{%0,%1,%2,%3}, {%4,%5,%6,%7}, {%8,%9}, {%0,%1,%2,%3};" \
                 : "+f"((c)[0]), "+f"((c)[1]), "+f"((c)[2]), "+f"((c)[3]) \
                 : "r"((a)[0]), "r"((a)[1]), "r"((a)[2]), "r"((a)[3]), \
                   "r"((b)[0]), "r"((b)[1]))

#define LDMX4(r0, r1, r2, r3, a) \
    asm volatile("ldmatrix.sync.aligned.m8n8.x4.shared.b16 {%0,%1,%2,%3}, [%4];" \
                 : "=r"(r0), "=r"(r1), "=r"(r2), "=r"(r3) : "r"(a))

__device__ __forceinline__ float gelu_tanh(float x) {
    const float c = 0.7978845608028654f;
    float x3 = x * x * x;
    return 0.5f * x * (1.0f + tanhf(c * (x + 0.044715f * x3)));
}
__device__ __forceinline__ void lse_merge(float& m, float& s, float m2, float s2) {
    float M = fmaxf(m, m2);
    if (M == -INFINITY) { m = M; s = 0.f; return; }
    float e1 = (m  == -INFINITY) ? 0.f : expf(m  - M);
    float e2 = (m2 == -INFINITY) ? 0.f : expf(m2 - M);
    s = s * e1 + s2 * e2;
    m = M;
}

// ---------------- embed ---------------------------------------------------------
__global__ void embed_kernel(const int* __restrict__ x0,
                             const float* __restrict__ wte,
                             const float* __restrict__ wpe,
                             float* __restrict__ x) {
    int i = blockIdx.x * blockDim.x + threadIdx.x;
    if (i >= NM * NE) return;
    int tok = i / NE, e = i - tok * NE;
    int t = tok % NTOK;
    int id = x0[tok];
    x[i] = wte[(size_t)id * NE + e] + wpe[(size_t)t * NE + e];
}

// ---------------- layernorm -> split bf16 (warp per token) -----------------------
__global__ void __launch_bounds__(256) ln_split2(const float* __restrict__ x,
                                                 const float* __restrict__ w,
                                                 const float* __restrict__ b,
                                                 bf16* __restrict__ oh,
                                                 bf16* __restrict__ ol) {
    int warp = threadIdx.x >> 5, lane = threadIdx.x & 31;
    int tok = blockIdx.x * 8 + warp;
    const float* row = x + (size_t)tok * NE;

    float v[24];
    float s = 0.f;
#pragma unroll
    for (int j = 0; j < 6; ++j) {
        float4 f = *(const float4*)(row + j * 128 + lane * 4);
        v[4*j] = f.x; v[4*j+1] = f.y; v[4*j+2] = f.z; v[4*j+3] = f.w;
        s += (f.x + f.y) + (f.z + f.w);
    }
#pragma unroll
    for (int o = 16; o > 0; o >>= 1) s += __shfl_xor_sync(0xFFFFFFFFu, s, o);
    float mean = s * (1.0f / NE);

    float var = 0.f;
#pragma unroll
    for (int i = 0; i < 24; ++i) { float d = v[i] - mean; var += d * d; }
#pragma unroll
    for (int o = 16; o > 0; o >>= 1) var += __shfl_xor_sync(0xFFFFFFFFu, var, o);
    float rstd = rsqrtf(var * (1.0f / NE) + 1e-6f);

#pragma unroll
    for (int j = 0; j < 6; ++j) {
        float4 w4 = *(const float4*)(w + j * 128 + lane * 4);
        float4 b4 = *(const float4*)(b + j * 128 + lane * 4);
        float o0 = (v[4*j]   - mean) * rstd * w4.x + b4.x;
        float o1 = (v[4*j+1] - mean) * rstd * w4.y + b4.y;
        float o2 = (v[4*j+2] - mean) * rstd * w4.z + b4.z;
        float o3 = (v[4*j+3] - mean) * rstd * w4.w + b4.w;
        bf16 h0 = __float2bfloat16(o0), h1 = __float2bfloat16(o1);
        bf16 h2 = __float2bfloat16(o2), h3 = __float2bfloat16(o3);
        uint2 H, L;
        { __nv_bfloat162 p; p.x = h0; p.y = h1; H.x = *(uint32_t*)&p;
          p.x = h2; p.y = h3; H.y = *(uint32_t*)&p; }
        L.x = packbf(o0 - __bfloat162float(h0), o1 - __bfloat162float(h1));
        L.y = packbf(o2 - __bfloat162float(h2), o3 - __bfloat162float(h3));
        *(uint2*)(oh + (size_t)tok * NE + j * 128 + lane * 4) = H;
        *(uint2*)(ol + (size_t)tok * NE + j * 128 + lane * 4) = L;
    }
}

// ---------------- vectorized split (wte) ------------------------------------------
__global__ void split4(const float* __restrict__ x,
                       bf16* __restrict__ hi, bf16* __restrict__ lo, int n4) {
    int i = blockIdx.x * blockDim.x + threadIdx.x;
    if (i >= n4) return;
    float4 v = ((const float4*)x)[i];
    bf16 h0 = __float2bfloat16(v.x), h1 = __float2bfloat16(v.y);
    bf16 h2 = __float2bfloat16(v.z), h3 = __float2bfloat16(v.w);
    uint2 H, L;
    { __nv_bfloat162 p; p.x = h0; p.y = h1; H.x = *(uint32_t*)&p;
      p.x = h2; p.y = h3; H.y = *(uint32_t*)&p; }
    L.x = packbf(v.x - __bfloat162float(h0), v.y - __bfloat162float(h1));
    L.y = packbf(v.z - __bfloat162float(h2), v.w - __bfloat162float(h3));
    ((uint2*)hi)[i] = H;
    ((uint2*)lo)[i] = L;
}

// ---------------- vectorized transpose-split: in[K,N] -> out[N,K] -----------------
__global__ void __launch_bounds__(256) tsplit2(const float* __restrict__ in,
                                               bf16* __restrict__ oh,
                                               bf16* __restrict__ ol,
                                               int K, int N) {
    __shared__ float t[32][65];
    int tid = threadIdx.x;
    int kb = blockIdx.y * 32, nb = blockIdx.x * 64;
#pragma unroll
    for (int i = 0; i < 2; ++i) {
        int id = tid + 256 * i;
        int r = id >> 4, c4 = (id & 15) * 4;
        float4 v = *(const float4*)(in + (size_t)(kb + r) * N + nb + c4);
        t[r][c4] = v.x; t[r][c4+1] = v.y; t[r][c4+2] = v.z; t[r][c4+3] = v.w;
    }
    __syncthreads();
#pragma unroll
    for (int i = 0; i < 4; ++i) {
        int id = tid + 256 * i;
        int n = id >> 4, kp = id & 15;
        float v0 = t[2*kp][n], v1 = t[2*kp+1][n];
        bf16 h0 = __float2bfloat16(v0), h1 = __float2bfloat16(v1);
        uint32_t H;
        { __nv_bfloat162 p; p.x = h0; p.y = h1; H = *(uint32_t*)&p; }
        uint32_t L = packbf(v0 - __bfloat162float(h0), v1 - __bfloat162float(h1));
        size_t idx = (size_t)(nb + n) * K + kb + 2 * kp;
        *(uint32_t*)(oh + idx) = H;
        *(uint32_t*)(ol + idx) = L;
    }
}

// ---------------- GEMM v3: cp.async + ldmatrix split-bf16 HMMA, occ 2 --------------
// C = epi(A[M,K] * B^T), B stored [N,K].
// EPI: 0 none, 1 +R, 2 gelu, 3 fp32 out + logsumexp partials (PM/PS).
// OUT: 0 fp32 C, 1 bf16 hi/lo pair. WM: warps in M (2 -> BN=128, 4 -> BN=64).
template<int EPI, int OUT, int WM>
__global__ void __launch_bounds__(256, 2) gemm2(
    const bf16* __restrict__ Ah, const bf16* __restrict__ Al,
    const bf16* __restrict__ Bh, const bf16* __restrict__ Bl,
    float* __restrict__ C, bf16* __restrict__ Ch, bf16* __restrict__ Cl,
    const float* __restrict__ R, float* __restrict__ PM, float* __restrict__ PS,
    int M, int N, int K)
{
    constexpr int WN = 8 / WM;
    constexpr int BN = WN * 32;
    constexpr int MT = 128 / (16 * WM);
    extern __shared__ bf16 smem[];
    bf16* Ash = smem;                // [2][128][40]
    bf16* Asl = Ash + 2 * 128 * 40;
    bf16* Bsh = Asl + 2 * 128 * 40;  // [2][BN][40]
    bf16* Bsl = Bsh + 2 * BN * 40;

    const int tid = threadIdx.x;
    const int lane = tid & 31, wid = tid >> 5;
    const int wm = wid / WN, wn = wid % WN;
    const int g = lane >> 2, tg = lane & 3;
    const int m0 = blockIdx.y * 128;
    const int n0 = blockIdx.x * BN;

    // ldmatrix per-lane address components (bytes; row stride = 80 B)
    const int a_sub = (lane & 7) + ((lane >> 3) & 1) * 8;  // row within m16 frag
    const int a_c8  = (lane >> 4) * 8;                     // k col 0 or 8
    const int b_sub = (lane & 7) + (lane >> 4) * 8;        // row within n16 pair
    const int b_c8  = ((lane >> 3) & 1) * 8;

    const uint32_t ash_u = smem_u32(Ash);
    const uint32_t asl_u = smem_u32(Asl);
    const uint32_t bsh_u = smem_u32(Bsh);
    const uint32_t bsl_u = smem_u32(Bsl);

    float acc[MT][4][4];
#pragma unroll
    for (int a = 0; a < MT; ++a)
#pragma unroll
        for (int b = 0; b < 4; ++b)
#pragma unroll
            for (int c = 0; c < 4; ++c) acc[a][b][c] = 0.f;

    auto load_stage = [&](int st, int k0) {
#pragma unroll
        for (int i = 0; i < 2; ++i) {
            int c = tid + 256 * i;
            int r = c >> 2, cq = (c & 3) * 8;
            cpa16(&Ash[(st * 128 + r) * 40 + cq], Ah + (size_t)(m0 + r) * K + k0 + cq);
            cpa16(&Asl[(st * 128 + r) * 40 + cq], Al + (size_t)(m0 + r) * K + k0 + cq);
        }
        for (int c = tid; c < BN * 4; c += 256) {
            int r = c >> 2, cq = (c & 3) * 8;
            int n = n0 + r;
            int ok = n < N;
            size_t src = (size_t)(ok ? n : 0) * K + k0 + cq;
            cpa16z(&Bsh[(st * BN + r) * 40 + cq], Bh + src, ok ? 16 : 0);
            cpa16z(&Bsl[(st * BN + r) * 40 + cq], Bl + src, ok ? 16 : 0);
        }
    };

    load_stage(0, 0);
    CP_COMMIT();
    const int nk = K / 32;
    for (int it = 0; it < nk; ++it) {
        int st = it & 1;
        if (it + 1 < nk) { load_stage(st ^ 1, (it + 1) * 32); CP_COMMIT(); CP_WAIT(1); }
        else            { CP_WAIT(0); }
        __syncthreads();
#pragma unroll
        for (int kk = 0; kk < 32; kk += 16) {
            // B fragments: 2 ldmatrix.x4 per hi/lo cover all 4 n-frags
            uint32_t bhf[4][2], blf[4][2];
#pragma unroll
            for (int p = 0; p < 2; ++p) {
                int cb = st * BN + wn * 32 + p * 16;
                uint32_t off = (uint32_t)(cb + b_sub) * 80 + (uint32_t)(kk + b_c8) * 2;
                LDMX4(bhf[2*p][0], bhf[2*p][1], bhf[2*p+1][0], bhf[2*p+1][1], bsh_u + off);
                LDMX4(blf[2*p][0], blf[2*p][1], blf[2*p+1][0], blf[2*p+1][1], bsl_u + off);
            }
            // m-frags in halves of 2 (register pressure, occ 2)
#pragma unroll
            for (int mh = 0; mh < MT; mh += 2) {
                uint32_t ah[2][4], al[2][4];
#pragma unroll
                for (int q = 0; q < 2 && mh + q < MT; ++q) {
                    int rb = st * 128 + wm * MT * 16 + (mh + q) * 16;
                    uint32_t off = (uint32_t)(rb + a_sub) * 80 + (uint32_t)(kk + a_c8) * 2;
                    LDMX4(ah[q][0], ah[q][1], ah[q][2], ah[q][3], ash_u + off);
                    LDMX4(al[q][0], al[q][1], al[q][2], al[q][3], asl_u + off);
                }
#pragma unroll
                for (int q = 0; q < 2 && mh + q < MT; ++q)
#pragma unroll
                    for (int nt = 0; nt < 4; ++nt) {
                        MMA16816(acc[mh + q][nt], ah[q], bhf[nt]);
                        MMA16816(acc[mh + q][nt], ah[q], blf[nt]);
                        MMA16816(acc[mh + q][nt], al[q], bhf[nt]);
                    }
            }
        }
        __syncthreads();
    }

    if (EPI == 3) {
        int tile = blockIdx.x * WN + wn;
#pragma unroll
        for (int mt = 0; mt < MT; ++mt) {
#pragma unroll
            for (int r = 0; r < 2; ++r) {
                int m = m0 + wm * MT * 16 + mt * 16 + g + 8 * r;
                float vals[8];
                float rm = -INFINITY;
#pragma unroll
                for (int nt = 0; nt < 4; ++nt)
#pragma unroll
                    for (int j = 0; j < 2; ++j) {
                        int n = n0 + wn * 32 + nt * 8 + 2 * tg + j;
                        float v = acc[mt][nt][2 * r + j];
                        if (n < N) {
                            C[(size_t)m * N + n] = v;
                            rm = fmaxf(rm, v);
                            vals[nt * 2 + j] = v;
                        } else {
                            vals[nt * 2 + j] = -INFINITY;
                        }
                    }
                rm = fmaxf(rm, __shfl_xor_sync(0xFFFFFFFFu, rm, 1));
                rm = fmaxf(rm, __shfl_xor_sync(0xFFFFFFFFu, rm, 2));
                float s = 0.f;
                if (rm != -INFINITY) {
#pragma unroll
                    for (int i = 0; i < 8; ++i)
                        s += (vals[i] == -INFINITY) ? 0.f : expf(vals[i] - rm);
                }
                s += __shfl_xor_sync(0xFFFFFFFFu, s, 1);
                s += __shfl_xor_sync(0xFFFFFFFFu, s, 2);
                if (tg == 0) {
                    PM[(size_t)m * NTP + tile] = rm;
                    PS[(size_t)m * NTP + tile] = s;
                }
            }
        }
        return;
    }

#pragma unroll
    for (int mt = 0; mt < MT; ++mt) {
#pragma unroll
        for (int nt = 0; nt < 4; ++nt) {
            int nbase = n0 + wn * 32 + nt * 8 + 2 * tg;
#pragma unroll
            for (int r = 0; r < 2; ++r) {
                int m = m0 + wm * MT * 16 + mt * 16 + g + 8 * r;
                float v0 = acc[mt][nt][2 * r + 0];
                float v1 = acc[mt][nt][2 * r + 1];
                if (EPI == 1) {
                    if (nbase     < N) v0 += R[(size_t)m * N + nbase];
                    if (nbase + 1 < N) v1 += R[(size_t)m * N + nbase + 1];
                }
                if (EPI == 2) { v0 = gelu_tanh(v0); v1 = gelu_tanh(v1); }
                if (OUT == 0) {
                    if (nbase     < N) C[(size_t)m * N + nbase]     = v0;
                    if (nbase + 1 < N) C[(size_t)m * N + nbase + 1] = v1;
                } else {
                    bf16 h0 = __float2bfloat16(v0);
                    bf16 h1 = __float2bfloat16(v1);
                    float l0 = v0 - __bfloat162float(h0);
                    float l1 = v1 - __bfloat162float(h1);
                    __nv_bfloat162 hp; hp.x = h0; hp.y = h1;
                    *(uint32_t*)(Ch + (size_t)m * N + nbase) = *(uint32_t*)&hp;
                    *(uint32_t*)(Cl + (size_t)m * N + nbase) = packbf(l0, l1);
                }
            }
        }
    }
}

// ---------------- flash attention (split-bf16 MMA, causal, online softmax) --------
#define FP 72
__global__ void __launch_bounds__(128) flash_kernel(
    const bf16* __restrict__ qh, const bf16* __restrict__ ql,
    bf16* __restrict__ yh, bf16* __restrict__ yl)
{
    __shared__ bf16 Kh[64][FP], Kl[64][FP], Vh[64][FP], Vl[64][FP];
    const int bh = blockIdx.y, b = bh / NH, h = bh % NH;
    const int t0 = blockIdx.x * 64;
    const int tid = threadIdx.x, lane = tid & 31, w = tid >> 5;
    const int g = lane >> 2, tg = lane & 3;

#pragma unroll
    for (int i = 0; i < 4; ++i) {
        int c = tid + 128 * i;
        int r = c >> 3, c8 = (c & 7) * 8;
        *(float4*)&Kh[r][c8] = *(const float4*)(qh + (size_t)(b * NTOK + t0 + r) * N3 + h * DH + c8);
        *(float4*)&Kl[r][c8] = *(const float4*)(ql + (size_t)(b * NTOK + t0 + r) * N3 + h * DH + c8);
    }
    __syncthreads();
    uint32_t qfh[4][4], qfl[4][4];
    {
        int rb = w * 16;
#pragma unroll
        for (int kf = 0; kf < 4; ++kf) {
            qfh[kf][0] = *(const uint32_t*)&Kh[rb + g    ][kf * 16 + 2 * tg];
            qfh[kf][1] = *(const uint32_t*)&Kh[rb + g + 8][kf * 16 + 2 * tg];
            qfh[kf][2] = *(const uint32_t*)&Kh[rb + g    ][kf * 16 + 8 + 2 * tg];
            qfh[kf][3] = *(const uint32_t*)&Kh[rb + g + 8][kf * 16 + 8 + 2 * tg];
            qfl[kf][0] = *(const uint32_t*)&Kl[rb + g    ][kf * 16 + 2 * tg];
            qfl[kf][1] = *(const uint32_t*)&Kl[rb + g + 8][kf * 16 + 2 * tg];
            qfl[kf][2] = *(const uint32_t*)&Kl[rb + g    ][kf * 16 + 8 + 2 * tg];
            qfl[kf][3] = *(const uint32_t*)&Kl[rb + g + 8][kf * 16 + 8 + 2 * tg];
        }
    }
    __syncthreads();

    float mr[2] = {-1e30f, -1e30f};
    float lr[2] = {0.f, 0.f};
    float acco[8][4];
#pragma unroll
    for (int i = 0; i < 8; ++i)
#pragma unroll
        for (int j = 0; j < 4; ++j) acco[i][j] = 0.f;

    const int nsb = blockIdx.x + 1;
    for (int sb = 0; sb < nsb; ++sb) {
        int s0 = sb * 64;
#pragma unroll
        for (int i = 0; i < 4; ++i) {
            int c = tid + 128 * i;
            int r = c >> 3, c8 = (c & 7) * 8;
            const size_t rowoff = (size_t)(b * NTOK + s0 + r) * N3;
            *(float4*)&Kh[r][c8] = *(const float4*)(qh + rowoff + NE + h * DH + c8);
            *(float4*)&Kl[r][c8] = *(const float4*)(ql + rowoff + NE + h * DH + c8);
            float4 v4h = *(const float4*)(qh + rowoff + 2 * NE + h * DH + c8);
            float4 v4l = *(const float4*)(ql + rowoff + 2 * NE + h * DH + c8);
            const bf16* eh = (const bf16*)&v4h;
            const bf16* el = (const bf16*)&v4l;
#pragma unroll
            for (int j = 0; j < 8; ++j) { Vh[c8 + j][r] = eh[j]; Vl[c8 + j][r] = el[j]; }
        }
        __syncthreads();

        float accs[8][4];
#pragma unroll
        for (int i = 0; i < 8; ++i)
#pragma unroll
            for (int j = 0; j < 4; ++j) accs[i][j] = 0.f;
#pragma unroll
        for (int nt = 0; nt < 8; ++nt) {
#pragma unroll
            for (int kf = 0; kf < 4; ++kf) {
                uint32_t kbh[2], kbl[2];
                kbh[0] = *(const uint32_t*)&Kh[nt * 8 + g][kf * 16 + 2 * tg];
                kbh[1] = *(const uint32_t*)&Kh[nt * 8 + g][kf * 16 + 8 + 2 * tg];
                kbl[0] = *(const uint32_t*)&Kl[nt * 8 + g][kf * 16 + 2 * tg];
                kbl[1] = *(const uint32_t*)&Kl[nt * 8 + g][kf * 16 + 8 + 2 * tg];
                MMA16816(accs[nt], qfh[kf], kbh);
                MMA16816(accs[nt], qfh[kf], kbl);
                MMA16816(accs[nt], qfl[kf], kbh);
            }
        }

#pragma unroll
        for (int r = 0; r < 2; ++r) {
            int row = t0 + w * 16 + g + 8 * r;
            float rm = -1e30f;
#pragma unroll
            for (int nt = 0; nt < 8; ++nt) {
#pragma unroll
                for (int j = 0; j < 2; ++j) {
                    int col = s0 + nt * 8 + 2 * tg + j;
                    float v = accs[nt][2 * r + j] * 0.125f;
                    if (col > row) v = -1e30f;
                    accs[nt][2 * r + j] = v;
                    rm = fmaxf(rm, v);
                }
            }
            rm = fmaxf(rm, __shfl_xor_sync(0xFFFFFFFFu, rm, 1));
            rm = fmaxf(rm, __shfl_xor_sync(0xFFFFFFFFu, rm, 2));
            float nm = fmaxf(mr[r], rm);
            float fac = __expf(mr[r] - nm);
            mr[r] = nm;
            float rs = 0.f;
#pragma unroll
            for (int nt = 0; nt < 8; ++nt) {
#pragma unroll
                for (int j = 0; j < 2; ++j) {
                    float p = __expf(accs[nt][2 * r + j] - nm);
                    accs[nt][2 * r + j] = p;
                    rs += p;
                }
            }
            rs += __shfl_xor_sync(0xFFFFFFFFu, rs, 1);
            rs += __shfl_xor_sync(0xFFFFFFFFu, rs, 2);
            lr[r] = lr[r] * fac + rs;
#pragma unroll
            for (int nt = 0; nt < 8; ++nt) {
                acco[nt][2 * r + 0] *= fac;
                acco[nt][2 * r + 1] *= fac;
            }
        }

#pragma unroll
        for (int kf2 = 0; kf2 < 4; ++kf2) {
            uint32_t pah[4], pal[4];
            float p00 = accs[2 * kf2][0],     p01 = accs[2 * kf2][1];
            float p10 = accs[2 * kf2][2],     p11 = accs[2 * kf2][3];
            float p20 = accs[2 * kf2 + 1][0], p21 = accs[2 * kf2 + 1][1];
            float p30 = accs[2 * kf2 + 1][2], p31 = accs[2 * kf2 + 1][3];
            pah[0] = packbf(p00, p01); pah[1] = packbf(p10, p11);
            pah[2] = packbf(p20, p21); pah[3] = packbf(p30, p31);
            __nv_bfloat162* hp;
            hp = (__nv_bfloat162*)&pah[0];
            pal[0] = packbf(p00 - __bfloat162float(hp->x), p01 - __bfloat162float(hp->y));
            hp = (__nv_bfloat162*)&pah[1];
            pal[1] = packbf(p10 - __bfloat162float(hp->x), p11 - __bfloat162float(hp->y));
            hp = (__nv_bfloat162*)&pah[2];
            pal[2] = packbf(p20 - __bfloat162float(hp->x), p21 - __bfloat162float(hp->y));
            hp = (__nv_bfloat162*)&pah[3];
            pal[3] = packbf(p30 - __bfloat162float(hp->x), p31 - __bfloat162float(hp->y));
#pragma unroll
            for (int nt2 = 0; nt2 < 8; ++nt2) {
                uint32_t vbh[2], vbl[2];
                vbh[0] = *(const uint32_t*)&Vh[nt2 * 8 + g][kf2 * 16 + 2 * tg];
                vbh[1] = *(const uint32_t*)&Vh[nt2 * 8 + g][kf2 * 16 + 8 + 2 * tg];
                vbl[0] = *(const uint32_t*)&Vl[nt2 * 8 + g][kf2 * 16 + 2 * tg];
                vbl[1] = *(const uint32_t*)&Vl[nt2 * 8 + g][kf2 * 16 + 8 + 2 * tg];
                MMA16816(acco[nt2], pah, vbh);
                MMA16816(acco[nt2], pah, vbl);
                MMA16816(acco[nt2], pal, vbh);
            }
        }
        __syncthreads();
    }

#pragma unroll
    for (int r = 0; r < 2; ++r) {
        float inv = 1.0f / lr[r];
        int row = t0 + w * 16 + g + 8 * r;
#pragma unroll
        for (int nt2 = 0; nt2 < 8; ++nt2) {
            float v0 = acco[nt2][2 * r + 0] * inv;
            float v1 = acco[nt2][2 * r + 1] * inv;
            bf16 h0 = __float2bfloat16(v0);
            bf16 h1 = __float2bfloat16(v1);
            size_t idx = (size_t)(b * NTOK + row) * NE + h * DH + nt2 * 8 + 2 * tg;
            __nv_bfloat162 hp; hp.x = h0; hp.y = h1;
            *(uint32_t*)(yh + idx) = *(uint32_t*)&hp;
            *(uint32_t*)(yl + idx) = packbf(v0 - __bfloat162float(h0), v1 - __bfloat162float(h1));
        }
    }
}

// ---------------- loss: merge logsumexp partials ----------------------------------
__global__ void __launch_bounds__(256) loss_rows2(const float* __restrict__ pm,
                                                  const float* __restrict__ ps,
                                                  const float* __restrict__ logits,
                                                  const int* __restrict__ tgt,
                                                  float* __restrict__ rl) {
    int row = blockIdx.x;
    int tid = threadIdx.x;
    __shared__ float sm[256], ss[256];

    float m = -INFINITY, s = 0.f;
    for (int i = tid; i < NTP; i += 256)
        lse_merge(m, s, pm[(size_t)row * NTP + i], ps[(size_t)row * NTP + i]);
    sm[tid] = m; ss[tid] = s; __syncthreads();
    for (int o = 128; o > 0; o >>= 1) {
        if (tid < o) {
            float mm = sm[tid], sv = ss[tid];
            lse_merge(mm, sv, sm[tid + o], ss[tid + o]);
            sm[tid] = mm; ss[tid] = sv;
        }
        __syncthreads();
    }
    if (tid == 0) {
        float lt = logits[(size_t)row * NV + tgt[row]];
        rl[row] = -(lt - sm[0] - logf(ss[0]));
    }
}

__global__ void __launch_bounds__(256) loss_final(const float* __restrict__ rl,
                                                  float* __restrict__ out) {
    __shared__ float red[256];
    int tid = threadIdx.x;
    float s = 0.f;
    for (int i = tid; i < NM; i += 256) s += rl[i];
    red[tid] = s; __syncthreads();
    for (int o = 128; o > 0; o >>= 1) { if (tid < o) red[tid] += red[tid + o]; __syncthreads(); }
    if (tid == 0) out[0] = red[0] * (1.0f / NM);
}

// ---------------- host orchestration ------------------------------------------------
extern "C" void kernel_launch(void* const* d_in, const int* in_sizes, int n_in,
                              void* d_out, int out_size) {
    const int*   x0    = (const int*)  d_in[0];
    const int*   tgt   = (const int*)  d_in[1];
    const float* wte   = (const float*)d_in[2];
    const float* wpe   = (const float*)d_in[3];
    const float* ln1w  = (const float*)d_in[4];
    const float* ln1b  = (const float*)d_in[5];
    const float* Wqkv  = (const float*)d_in[6];
    const float* Wo    = (const float*)d_in[7];
    const float* ln2w  = (const float*)d_in[8];
    const float* ln2b  = (const float*)d_in[9];
    const float* Wfc   = (const float*)d_in[10];
    const float* Wproj = (const float*)d_in[11];
    const float* lnfw  = (const float*)d_in[12];
    const float* lnfb  = (const float*)d_in[13];

    float *px, *pl, *prl, *ppm, *pps;
    bf16 *pwth, *pwtl, *pwteh, *pwtel, *plnh, *plnl, *pqh, *pql, *pyh, *pyl, *pfh, *pfl;
    cudaGetSymbolAddress((void**)&px,  g_x);
    cudaGetSymbolAddress((void**)&pl,  g_logits);
    cudaGetSymbolAddress((void**)&prl, g_rl);
    cudaGetSymbolAddress((void**)&ppm, g_pm);
    cudaGetSymbolAddress((void**)&pps, g_ps);
    cudaGetSymbolAddress((void**)&pwth, g_wth);
    cudaGetSymbolAddress((void**)&pwtl, g_wtl);
    cudaGetSymbolAddress((void**)&pwteh, g_wteh);
    cudaGetSymbolAddress((void**)&pwtel, g_wtel);
    cudaGetSymbolAddress((void**)&plnh, g_lnh);
    cudaGetSymbolAddress((void**)&plnl, g_lnl);
    cudaGetSymbolAddress((void**)&pqh, g_qkvh);
    cudaGetSymbolAddress((void**)&pql, g_qkvl);
    cudaGetSymbolAddress((void**)&pyh, g_yh);
    cudaGetSymbolAddress((void**)&pyl, g_yl);
    cudaGetSymbolAddress((void**)&pfh, g_fch);
    cudaGetSymbolAddress((void**)&pfl, g_fcl);

    const int SM_WM2 = (2 * 128 * 40 * 2 + 2 * 128 * 40 * 2) * 2;  // 81920 B
    const int SM_WM4 = (2 * 128 * 40 * 2 + 2 * 64  * 40 * 2) * 2;  // 61440 B
    cudaFuncSetAttribute(gemm2<0,1,2>, cudaFuncAttributeMaxDynamicSharedMemorySize, SM_WM2);
    cudaFuncSetAttribute(gemm2<2,1,2>, cudaFuncAttributeMaxDynamicSharedMemorySize, SM_WM2);
    cudaFuncSetAttribute(gemm2<3,0,2>, cudaFuncAttributeMaxDynamicSharedMemorySize, SM_WM2);
    cudaFuncSetAttribute(gemm2<1,0,4>, cudaFuncAttributeMaxDynamicSharedMemorySize, SM_WM4);

    // weight transpose+split (vectorized)
    for (int l = 0; l < NL; ++l) {
        size_t off = (size_t)l * LPL;
        tsplit2<<<dim3(N3 / 64, NE / 32), 256>>>(
            Wqkv + (size_t)l * NE * N3, pwth + off, pwtl + off, NE, N3);
        off += LQKV;
        tsplit2<<<dim3(NE / 64, NE / 32), 256>>>(
            Wo + (size_t)l * NE * NE, pwth + off, pwtl + off, NE, NE);
        off += LWO;
        tsplit2<<<dim3(N4 / 64, NE / 32), 256>>>(
            Wfc + (size_t)l * NE * N4, pwth + off, pwtl + off, NE, N4);
        off += LWFC;
        tsplit2<<<dim3(NE / 64, N4 / 32), 256>>>(
            Wproj + (size_t)l * N4 * NE, pwth + off, pwtl + off, N4, NE);
    }
    {
        int n4 = (NV * NE) / 4;
        split4<<<(n4 + 255) / 256, 256>>>(wte, pwteh, pwtel, n4);
    }

    embed_kernel<<<(NM * NE + 255) / 256, 256>>>(x0, wte, wpe, px);

    for (int l = 0; l < NL; ++l) {
        size_t off = (size_t)l * LPL;
        ln_split2<<<NM / 8, 256>>>(px, ln1w + (size_t)l * NE, ln1b + (size_t)l * NE, plnh, plnl);
        gemm2<0,1,2><<<dim3(N3 / 128, NM / 128), 256, SM_WM2>>>(
            plnh, plnl, pwth + off, pwtl + off, nullptr, pqh, pql, nullptr,
            nullptr, nullptr, NM, N3, NE);
        flash_kernel<<<dim3(NTOK / 64, NB * NH), 128>>>(pqh, pql, pyh, pyl);
        gemm2<1,0,4><<<dim3(NE / 64, NM / 128), 256, SM_WM4>>>(
            pyh, pyl, pwth + off + LQKV, pwtl + off + LQKV, px, nullptr, nullptr, px,
            nullptr, nullptr, NM, NE, NE);
        ln_split2<<<NM / 8, 256>>>(px, ln2w + (size_t)l * NE, ln2b + (size_t)l * NE, plnh, plnl);
        gemm2<2,1,2><<<dim3(N4 / 128, NM / 128), 256, SM_WM2>>>(
            plnh, plnl, pwth + off + LQKV + LWO, pwtl + off + LQKV + LWO,
            nullptr, pfh, pfl, nullptr, nullptr, nullptr, NM, N4, NE);
        gemm2<1,0,4><<<dim3(NE / 64, NM / 128), 256, SM_WM4>>>(
            pfh, pfl, pwth + off + LQKV + LWO + LWFC, pwtl + off + LQKV + LWO + LWFC,
            px, nullptr, nullptr, px, nullptr, nullptr, NM, NE, N4);
    }

    ln_split2<<<NM / 8, 256>>>(px, lnfw, lnfb, plnh, plnl);

    const size_t logits_elems = (size_t)NM * NV;
    float* logits = ((size_t)out_size >= logits_elems) ? (float*)d_out : pl;
    gemm2<3,0,2><<<dim3(NTN, NM / 128), 256, SM_WM2>>>(
        plnh, plnl, pwteh, pwtel, logits, nullptr, nullptr, nullptr,
        ppm, pps, NM, NV, NE);

    loss_rows2<<<NM, 256>>>(ppm, pps, logits, tgt, prl);
    if ((size_t)out_size > logits_elems) {
        loss_final<<<1, 256>>>(prl, (float*)d_out + logits_elems);
    } else if (logits != (float*)d_out) {
        loss_final<<<1, 256>>>(prl, (float*)d_out);
    }
}

// round 7
// speedup vs baseline: 2.7060x; 1.0552x over previous
#include <cuda_runtime.h>
#include <cuda_bf16.h>
#include <math.h>
#include <stdint.h>

// GPT-2 small fwd: B=2 T=1024 E=768 H=12 L=6 V=50257
#define NB 2
#define NTOK 1024
#define NE 768
#define NH 12
#define DH 64
#define NL 6
#define NV 50257
#define NM (NB*NTOK)
#define N3 (3*NE)
#define N4 (4*NE)

#define LQKV (N3*NE)
#define LWO  (NE*NE)
#define LWFC (N4*NE)
#define LWPR (NE*N4)
#define LPL  (LQKV+LWO+LWFC+LWPR)

#define NTN 393          // ceil(NV/128)
#define NTP (NTN*4)      // per-row lse partial tiles (4 warps per 128-col tile)

typedef __nv_bfloat16 bf16;

// ---------------- scratch ------------------------------------------------------
static __device__ float g_x  [NM*NE];
static __device__ float g_logits[(size_t)NM*NV];
static __device__ float g_rl [NM];
static __device__ float g_pm [(size_t)NM*NTP];
static __device__ float g_ps [(size_t)NM*NTP];
static __device__ bf16 g_wth[(size_t)NL*LPL];
static __device__ bf16 g_wtl[(size_t)NL*LPL];
static __device__ bf16 g_wteh[(size_t)NV*NE];
static __device__ bf16 g_wtel[(size_t)NV*NE];
static __device__ bf16 g_lnh[NM*NE];
static __device__ bf16 g_lnl[NM*NE];
static __device__ bf16 g_qkvh[NM*N3];
static __device__ bf16 g_qkvl[NM*N3];
static __device__ bf16 g_yh[NM*NE];
static __device__ bf16 g_yl[NM*NE];
static __device__ bf16 g_fch[NM*N4];
static __device__ bf16 g_fcl[NM*N4];

// ---------------- helpers -------------------------------------------------------
__device__ __forceinline__ uint32_t packbf(float a, float b) {
    __nv_bfloat162 t;
    t.x = __float2bfloat16(a);
    t.y = __float2bfloat16(b);
    return *(uint32_t*)&t;
}
__device__ __forceinline__ uint32_t smem_u32(const void* p) {
    uint32_t a;
    asm("{ .reg .u64 t; cvta.to.shared.u64 t, %1; cvt.u32.u64 %0, t; }" : "=r"(a) : "l"(p));
    return a;
}
__device__ __forceinline__ void cpa16(void* dst, const void* src) {
    uint32_t d = (uint32_t)__cvta_generic_to_shared(dst);
    asm volatile("cp.async.cg.shared.global [%0], [%1], 16;" :: "r"(d), "l"(src));
}
__device__ __forceinline__ void cpa16u(uint32_t d, const void* src) {
    asm volatile("cp.async.cg.shared.global [%0], [%1], 16;" :: "r"(d), "l"(src));
}
__device__ __forceinline__ void cpa16z(void* dst, const void* src, int sz) {
    uint32_t d = (uint32_t)__cvta_generic_to_shared(dst);
    asm volatile("cp.async.cg.shared.global [%0], [%1], 16, %2;" :: "r"(d), "l"(src), "r"(sz));
}
#define CP_COMMIT() asm volatile("cp.async.commit_group;")
#define CP_WAIT(n)  asm volatile("cp.async.wait_group %0;" :: "n"(n))

#define MMA16816(c, a, b) \
    asm volatile("mma.sync.aligned.m16n8k16.row.col.f32.bf16.bf16.f32 " \
                 "{%0,%1,%2,%3}, {%4,%5,%6,%7}, {%8,%9}, {%0,%1,%2,%3};" \
                 : "+f"((c)[0]), "+f"((c)[1]), "+f"((c)[2]), "+f"((c)[3]) \
                 : "r"((a)[0]), "r"((a)[1]), "r"((a)[2]), "r"((a)[3]), \
                   "r"((b)[0]), "r"((b)[1]))

#define LDMX4(r0, r1, r2, r3, a) \
    asm volatile("ldmatrix.sync.aligned.m8n8.x4.shared.b16 {%0,%1,%2,%3}, [%4];" \
                 : "=r"(r0), "=r"(r1), "=r"(r2), "=r"(r3) : "r"(a))
#define LDMX4T(r0, r1, r2, r3, a) \
    asm volatile("ldmatrix.sync.aligned.m8n8.x4.trans.shared.b16 {%0,%1,%2,%3}, [%4];" \
                 : "=r"(r0), "=r"(r1), "=r"(r2), "=r"(r3) : "r"(a))

__device__ __forceinline__ float gelu_tanh(float x) {
    const float c = 0.7978845608028654f;
    float x3 = x * x * x;
    return 0.5f * x * (1.0f + tanhf(c * (x + 0.044715f * x3)));
}
__device__ __forceinline__ void lse_merge(float& m, float& s, float m2, float s2) {
    float M = fmaxf(m, m2);
    if (M == -INFINITY) { m = M; s = 0.f; return; }
    float e1 = (m  == -INFINITY) ? 0.f : expf(m  - M);
    float e2 = (m2 == -INFINITY) ? 0.f : expf(m2 - M);
    s = s * e1 + s2 * e2;
    m = M;
}

// ---------------- embed ---------------------------------------------------------
__global__ void embed_kernel(const int* __restrict__ x0,
                             const float* __restrict__ wte,
                             const float* __restrict__ wpe,
                             float* __restrict__ x) {
    int i = blockIdx.x * blockDim.x + threadIdx.x;
    if (i >= NM * NE) return;
    int tok = i / NE, e = i - tok * NE;
    int t = tok % NTOK;
    int id = x0[tok];
    x[i] = wte[(size_t)id * NE + e] + wpe[(size_t)t * NE + e];
}

// ---------------- layernorm -> split bf16 (warp per token) -----------------------
__global__ void __launch_bounds__(256) ln_split2(const float* __restrict__ x,
                                                 const float* __restrict__ w,
                                                 const float* __restrict__ b,
                                                 bf16* __restrict__ oh,
                                                 bf16* __restrict__ ol) {
    int warp = threadIdx.x >> 5, lane = threadIdx.x & 31;
    int tok = blockIdx.x * 8 + warp;
    const float* row = x + (size_t)tok * NE;

    float v[24];
    float s = 0.f;
#pragma unroll
    for (int j = 0; j < 6; ++j) {
        float4 f = *(const float4*)(row + j * 128 + lane * 4);
        v[4*j] = f.x; v[4*j+1] = f.y; v[4*j+2] = f.z; v[4*j+3] = f.w;
        s += (f.x + f.y) + (f.z + f.w);
    }
#pragma unroll
    for (int o = 16; o > 0; o >>= 1) s += __shfl_xor_sync(0xFFFFFFFFu, s, o);
    float mean = s * (1.0f / NE);

    float var = 0.f;
#pragma unroll
    for (int i = 0; i < 24; ++i) { float d = v[i] - mean; var += d * d; }
#pragma unroll
    for (int o = 16; o > 0; o >>= 1) var += __shfl_xor_sync(0xFFFFFFFFu, var, o);
    float rstd = rsqrtf(var * (1.0f / NE) + 1e-6f);

#pragma unroll
    for (int j = 0; j < 6; ++j) {
        float4 w4 = *(const float4*)(w + j * 128 + lane * 4);
        float4 b4 = *(const float4*)(b + j * 128 + lane * 4);
        float o0 = (v[4*j]   - mean) * rstd * w4.x + b4.x;
        float o1 = (v[4*j+1] - mean) * rstd * w4.y + b4.y;
        float o2 = (v[4*j+2] - mean) * rstd * w4.z + b4.z;
        float o3 = (v[4*j+3] - mean) * rstd * w4.w + b4.w;
        bf16 h0 = __float2bfloat16(o0), h1 = __float2bfloat16(o1);
        bf16 h2 = __float2bfloat16(o2), h3 = __float2bfloat16(o3);
        uint2 H, L;
        { __nv_bfloat162 p; p.x = h0; p.y = h1; H.x = *(uint32_t*)&p;
          p.x = h2; p.y = h3; H.y = *(uint32_t*)&p; }
        L.x = packbf(o0 - __bfloat162float(h0), o1 - __bfloat162float(h1));
        L.y = packbf(o2 - __bfloat162float(h2), o3 - __bfloat162float(h3));
        *(uint2*)(oh + (size_t)tok * NE + j * 128 + lane * 4) = H;
        *(uint2*)(ol + (size_t)tok * NE + j * 128 + lane * 4) = L;
    }
}

// ---------------- vectorized split (wte) ------------------------------------------
__global__ void split4(const float* __restrict__ x,
                       bf16* __restrict__ hi, bf16* __restrict__ lo, int n4) {
    int i = blockIdx.x * blockDim.x + threadIdx.x;
    if (i >= n4) return;
    float4 v = ((const float4*)x)[i];
    bf16 h0 = __float2bfloat16(v.x), h1 = __float2bfloat16(v.y);
    bf16 h2 = __float2bfloat16(v.z), h3 = __float2bfloat16(v.w);
    uint2 H, L;
    { __nv_bfloat162 p; p.x = h0; p.y = h1; H.x = *(uint32_t*)&p;
      p.x = h2; p.y = h3; H.y = *(uint32_t*)&p; }
    L.x = packbf(v.x - __bfloat162float(h0), v.y - __bfloat162float(h1));
    L.y = packbf(v.z - __bfloat162float(h2), v.w - __bfloat162float(h3));
    ((uint2*)hi)[i] = H;
    ((uint2*)lo)[i] = L;
}

// ---------------- vectorized transpose-split: in[K,N] -> out[N,K] -----------------
__global__ void __launch_bounds__(256) tsplit2(const float* __restrict__ in,
                                               bf16* __restrict__ oh,
                                               bf16* __restrict__ ol,
                                               int K, int N) {
    __shared__ float t[32][65];
    int tid = threadIdx.x;
    int kb = blockIdx.y * 32, nb = blockIdx.x * 64;
#pragma unroll
    for (int i = 0; i < 2; ++i) {
        int id = tid + 256 * i;
        int r = id >> 4, c4 = (id & 15) * 4;
        float4 v = *(const float4*)(in + (size_t)(kb + r) * N + nb + c4);
        t[r][c4] = v.x; t[r][c4+1] = v.y; t[r][c4+2] = v.z; t[r][c4+3] = v.w;
    }
    __syncthreads();
#pragma unroll
    for (int i = 0; i < 4; ++i) {
        int id = tid + 256 * i;
        int n = id >> 4, kp = id & 15;
        float v0 = t[2*kp][n], v1 = t[2*kp+1][n];
        bf16 h0 = __float2bfloat16(v0), h1 = __float2bfloat16(v1);
        uint32_t H;
        { __nv_bfloat162 p; p.x = h0; p.y = h1; H = *(uint32_t*)&p; }
        uint32_t L = packbf(v0 - __bfloat162float(h0), v1 - __bfloat162float(h1));
        size_t idx = (size_t)(nb + n) * K + kb + 2 * kp;
        *(uint32_t*)(oh + idx) = H;
        *(uint32_t*)(ol + idx) = L;
    }
}

// ---------------- GEMM: cp.async + ldmatrix split-bf16 HMMA, occ 2 -----------------
// C = epi(A[M,K] * B^T), B stored [N,K].
// EPI: 0 none, 1 +R, 2 gelu, 3 fp32 out + logsumexp partials (PM/PS).
// OUT: 0 fp32 C, 1 bf16 hi/lo pair. WM: warps in M (2 -> BN=128, 4 -> BN=64).
template<int EPI, int OUT, int WM>
__global__ void __launch_bounds__(256, 2) gemm2(
    const bf16* __restrict__ Ah, const bf16* __restrict__ Al,
    const bf16* __restrict__ Bh, const bf16* __restrict__ Bl,
    float* __restrict__ C, bf16* __restrict__ Ch, bf16* __restrict__ Cl,
    const float* __restrict__ R, float* __restrict__ PM, float* __restrict__ PS,
    int M, int N, int K)
{
    constexpr int WN = 8 / WM;
    constexpr int BN = WN * 32;
    constexpr int MT = 128 / (16 * WM);
    extern __shared__ bf16 smem[];
    bf16* Ash = smem;                // [2][128][40]
    bf16* Asl = Ash + 2 * 128 * 40;
    bf16* Bsh = Asl + 2 * 128 * 40;  // [2][BN][40]
    bf16* Bsl = Bsh + 2 * BN * 40;

    const int tid = threadIdx.x;
    const int lane = tid & 31, wid = tid >> 5;
    const int wm = wid / WN, wn = wid % WN;
    const int g = lane >> 2, tg = lane & 3;
    const int m0 = blockIdx.y * 128;
    const int n0 = blockIdx.x * BN;

    const int a_sub = (lane & 7) + ((lane >> 3) & 1) * 8;
    const int a_c8  = (lane >> 4) * 8;
    const int b_sub = (lane & 7) + (lane >> 4) * 8;
    const int b_c8  = ((lane >> 3) & 1) * 8;

    const uint32_t ash_u = smem_u32(Ash);
    const uint32_t asl_u = smem_u32(Asl);
    const uint32_t bsh_u = smem_u32(Bsh);
    const uint32_t bsl_u = smem_u32(Bsl);

    float acc[MT][4][4];
#pragma unroll
    for (int a = 0; a < MT; ++a)
#pragma unroll
        for (int b = 0; b < 4; ++b)
#pragma unroll
            for (int c = 0; c < 4; ++c) acc[a][b][c] = 0.f;

    auto load_stage = [&](int st, int k0) {
#pragma unroll
        for (int i = 0; i < 2; ++i) {
            int c = tid + 256 * i;
            int r = c >> 2, cq = (c & 3) * 8;
            cpa16(&Ash[(st * 128 + r) * 40 + cq], Ah + (size_t)(m0 + r) * K + k0 + cq);
            cpa16(&Asl[(st * 128 + r) * 40 + cq], Al + (size_t)(m0 + r) * K + k0 + cq);
        }
        for (int c = tid; c < BN * 4; c += 256) {
            int r = c >> 2, cq = (c & 3) * 8;
            int n = n0 + r;
            int ok = n < N;
            size_t src = (size_t)(ok ? n : 0) * K + k0 + cq;
            cpa16z(&Bsh[(st * BN + r) * 40 + cq], Bh + src, ok ? 16 : 0);
            cpa16z(&Bsl[(st * BN + r) * 40 + cq], Bl + src, ok ? 16 : 0);
        }
    };

    load_stage(0, 0);
    CP_COMMIT();
    const int nk = K / 32;
    for (int it = 0; it < nk; ++it) {
        int st = it & 1;
        if (it + 1 < nk) { load_stage(st ^ 1, (it + 1) * 32); CP_COMMIT(); CP_WAIT(1); }
        else            { CP_WAIT(0); }
        __syncthreads();
#pragma unroll
        for (int kk = 0; kk < 32; kk += 16) {
            uint32_t bhf[4][2], blf[4][2];
#pragma unroll
            for (int p = 0; p < 2; ++p) {
                int cb = st * BN + wn * 32 + p * 16;
                uint32_t off = (uint32_t)(cb + b_sub) * 80 + (uint32_t)(kk + b_c8) * 2;
                LDMX4(bhf[2*p][0], bhf[2*p][1], bhf[2*p+1][0], bhf[2*p+1][1], bsh_u + off);
                LDMX4(blf[2*p][0], blf[2*p][1], blf[2*p+1][0], blf[2*p+1][1], bsl_u + off);
            }
#pragma unroll
            for (int mh = 0; mh < MT; mh += 2) {
                uint32_t ah[2][4], al[2][4];
#pragma unroll
                for (int q = 0; q < 2 && mh + q < MT; ++q) {
                    int rb = st * 128 + wm * MT * 16 + (mh + q) * 16;
                    uint32_t off = (uint32_t)(rb + a_sub) * 80 + (uint32_t)(kk + a_c8) * 2;
                    LDMX4(ah[q][0], ah[q][1], ah[q][2], ah[q][3], ash_u + off);
                    LDMX4(al[q][0], al[q][1], al[q][2], al[q][3], asl_u + off);
                }
#pragma unroll
                for (int q = 0; q < 2 && mh + q < MT; ++q)
#pragma unroll
                    for (int nt = 0; nt < 4; ++nt) {
                        MMA16816(acc[mh + q][nt], ah[q], bhf[nt]);
                        MMA16816(acc[mh + q][nt], ah[q], blf[nt]);
                        MMA16816(acc[mh + q][nt], al[q], bhf[nt]);
                    }
            }
        }
        __syncthreads();
    }

    if (EPI == 3) {
        int tile = blockIdx.x * WN + wn;
#pragma unroll
        for (int mt = 0; mt < MT; ++mt) {
#pragma unroll
            for (int r = 0; r < 2; ++r) {
                int m = m0 + wm * MT * 16 + mt * 16 + g + 8 * r;
                float vals[8];
                float rm = -INFINITY;
#pragma unroll
                for (int nt = 0; nt < 4; ++nt)
#pragma unroll
                    for (int j = 0; j < 2; ++j) {
                        int n = n0 + wn * 32 + nt * 8 + 2 * tg + j;
                        float v = acc[mt][nt][2 * r + j];
                        if (n < N) {
                            C[(size_t)m * N + n] = v;
                            rm = fmaxf(rm, v);
                            vals[nt * 2 + j] = v;
                        } else {
                            vals[nt * 2 + j] = -INFINITY;
                        }
                    }
                rm = fmaxf(rm, __shfl_xor_sync(0xFFFFFFFFu, rm, 1));
                rm = fmaxf(rm, __shfl_xor_sync(0xFFFFFFFFu, rm, 2));
                float s = 0.f;
                if (rm != -INFINITY) {
#pragma unroll
                    for (int i = 0; i < 8; ++i)
                        s += (vals[i] == -INFINITY) ? 0.f : expf(vals[i] - rm);
                }
                s += __shfl_xor_sync(0xFFFFFFFFu, s, 1);
                s += __shfl_xor_sync(0xFFFFFFFFu, s, 2);
                if (tg == 0) {
                    PM[(size_t)m * NTP + tile] = rm;
                    PS[(size_t)m * NTP + tile] = s;
                }
            }
        }
        return;
    }

#pragma unroll
    for (int mt = 0; mt < MT; ++mt) {
#pragma unroll
        for (int nt = 0; nt < 4; ++nt) {
            int nbase = n0 + wn * 32 + nt * 8 + 2 * tg;
#pragma unroll
            for (int r = 0; r < 2; ++r) {
                int m = m0 + wm * MT * 16 + mt * 16 + g + 8 * r;
                float v0 = acc[mt][nt][2 * r + 0];
                float v1 = acc[mt][nt][2 * r + 1];
                if (EPI == 1) {
                    if (nbase     < N) v0 += R[(size_t)m * N + nbase];
                    if (nbase + 1 < N) v1 += R[(size_t)m * N + nbase + 1];
                }
                if (EPI == 2) { v0 = gelu_tanh(v0); v1 = gelu_tanh(v1); }
                if (OUT == 0) {
                    if (nbase     < N) C[(size_t)m * N + nbase]     = v0;
                    if (nbase + 1 < N) C[(size_t)m * N + nbase + 1] = v1;
                } else {
                    bf16 h0 = __float2bfloat16(v0);
                    bf16 h1 = __float2bfloat16(v1);
                    float l0 = v0 - __bfloat162float(h0);
                    float l1 = v1 - __bfloat162float(h1);
                    __nv_bfloat162 hp; hp.x = h0; hp.y = h1;
                    *(uint32_t*)(Ch + (size_t)m * N + nbase) = *(uint32_t*)&hp;
                    *(uint32_t*)(Cl + (size_t)m * N + nbase) = packbf(l0, l1);
                }
            }
        }
    }
}

// ---------------- flash attention v2: ldmatrix + cp.async double-buffer ------------
// grid (NTOK/64, NB*NH), 128 threads (4 warps x 16 t-rows).
// K stored [s][d] (row-major, pad FP2); V stored [s][d]; V^T frags via ldmatrix.trans.
#define FP2 72
#define FTILE (64*FP2)
#define FSTG (4*FTILE)
#define FSMEM (2*FSTG*2)   // 73728 bytes

__global__ void __launch_bounds__(128) flash2(
    const bf16* __restrict__ qh, const bf16* __restrict__ ql,
    bf16* __restrict__ yh, bf16* __restrict__ yl)
{
    extern __shared__ bf16 fsm[];
    const int bh = blockIdx.y, b = bh / NH, h = bh % NH;
    const int t0 = blockIdx.x * 64;
    const int tid = threadIdx.x, lane = tid & 31, w = tid >> 5;
    const int g = lane >> 2, tg = lane & 3;
    const uint32_t smb = smem_u32(fsm);

    // Q fragments via direct global loads (one-time)
    uint32_t qfh[4][4], qfl[4][4];
    {
        const size_t base = (size_t)(b * NTOK + t0 + w * 16) * N3 + h * DH;
#pragma unroll
        for (int kf = 0; kf < 4; ++kf) {
            int c0 = kf * 16 + 2 * tg;
            qfh[kf][0] = *(const uint32_t*)(qh + base + (size_t)g * N3 + c0);
            qfh[kf][1] = *(const uint32_t*)(qh + base + (size_t)(g + 8) * N3 + c0);
            qfh[kf][2] = *(const uint32_t*)(qh + base + (size_t)g * N3 + c0 + 8);
            qfh[kf][3] = *(const uint32_t*)(qh + base + (size_t)(g + 8) * N3 + c0 + 8);
            qfl[kf][0] = *(const uint32_t*)(ql + base + (size_t)g * N3 + c0);
            qfl[kf][1] = *(const uint32_t*)(ql + base + (size_t)(g + 8) * N3 + c0);
            qfl[kf][2] = *(const uint32_t*)(ql + base + (size_t)g * N3 + c0 + 8);
            qfl[kf][3] = *(const uint32_t*)(ql + base + (size_t)(g + 8) * N3 + c0 + 8);
        }
    }

    // stage loader: tiles {Kh, Kl, Vh, Vl}, each 64 rows x 64 bf16 (pad FP2)
    auto loadKV = [&](int st, int sb) {
        int s0 = sb * 64;
#pragma unroll
        for (int i = 0; i < 16; ++i) {
            int id = tid + 128 * i;
            int tile = id >> 9;
            int rem = id & 511;
            int r = rem >> 3, c8 = (rem & 7) * 8;
            uint32_t dst = smb + (uint32_t)(st * FSTG + tile * FTILE + r * FP2 + c8) * 2;
            size_t rowoff = (size_t)(b * NTOK + s0 + r) * N3 + h * DH + c8;
            const bf16* src =
                (tile == 0) ? qh + rowoff + NE :
                (tile == 1) ? ql + rowoff + NE :
                (tile == 2) ? qh + rowoff + 2 * NE :
                              ql + rowoff + 2 * NE;
            cpa16u(dst, src);
        }
    };

    float mr[2] = {-1e30f, -1e30f};
    float lr[2] = {0.f, 0.f};
    float acco[8][4];
#pragma unroll
    for (int i = 0; i < 8; ++i)
#pragma unroll
        for (int j = 0; j < 4; ++j) acco[i][j] = 0.f;

    const int nsb = blockIdx.x + 1;
    loadKV(0, 0);
    CP_COMMIT();

    const int krow = ((lane >> 4) << 3) + (lane & 7);  // K ldmatrix row within 16
    const int kcol = ((lane >> 3) & 1) * 8;            // K ldmatrix col (d) 0/8
    const int vrow = lane & 15;                        // V trans ldmatrix row (s)
    const int vcol = (lane >> 4) * 8;                  // V trans ldmatrix col (d) 0/8

    for (int sb = 0; sb < nsb; ++sb) {
        int st = sb & 1;
        if (sb + 1 < nsb) { loadKV(st ^ 1, sb + 1); CP_COMMIT(); CP_WAIT(1); }
        else             { CP_WAIT(0); }
        __syncthreads();

        const uint32_t kb  = smb + (uint32_t)(st * FSTG) * 2;
        const uint32_t kbl = kb + FTILE * 2;
        const uint32_t vb  = kb + 2 * FTILE * 2;
        const uint32_t vbl = kb + 3 * FTILE * 2;

        // S = Q K^T (split 3-MMA), K frags via ldmatrix.x4 (non-trans)
        float accs[8][4];
#pragma unroll
        for (int i = 0; i < 8; ++i)
#pragma unroll
            for (int j = 0; j < 4; ++j) accs[i][j] = 0.f;
#pragma unroll
        for (int ntp = 0; ntp < 4; ++ntp) {
#pragma unroll
            for (int kf = 0; kf < 4; ++kf) {
                uint32_t off = (uint32_t)((ntp * 16 + krow) * FP2 + kf * 16 + kcol) * 2;
                uint32_t h0, h1, h2, h3, l0, l1, l2, l3;
                LDMX4(h0, h1, h2, h3, kb + off);
                LDMX4(l0, l1, l2, l3, kbl + off);
                uint32_t bh0[2] = {h0, h1}, bh1[2] = {h2, h3};
                uint32_t bl0[2] = {l0, l1}, bl1[2] = {l2, l3};
                MMA16816(accs[2*ntp],     qfh[kf], bh0);
                MMA16816(accs[2*ntp],     qfh[kf], bl0);
                MMA16816(accs[2*ntp],     qfl[kf], bh0);
                MMA16816(accs[2*ntp + 1], qfh[kf], bh1);
                MMA16816(accs[2*ntp + 1], qfh[kf], bl1);
                MMA16816(accs[2*ntp + 1], qfl[kf], bh1);
            }
        }

        // scale + causal mask + online softmax
        int s0 = sb * 64;
#pragma unroll
        for (int r = 0; r < 2; ++r) {
            int row = t0 + w * 16 + g + 8 * r;
            float rm = -1e30f;
#pragma unroll
            for (int nt = 0; nt < 8; ++nt) {
#pragma unroll
                for (int j = 0; j < 2; ++j) {
                    int col = s0 + nt * 8 + 2 * tg + j;
                    float v = accs[nt][2 * r + j] * 0.125f;
                    if (col > row) v = -1e30f;
                    accs[nt][2 * r + j] = v;
                    rm = fmaxf(rm, v);
                }
            }
            rm = fmaxf(rm, __shfl_xor_sync(0xFFFFFFFFu, rm, 1));
            rm = fmaxf(rm, __shfl_xor_sync(0xFFFFFFFFu, rm, 2));
            float nm = fmaxf(mr[r], rm);
            float fac = __expf(mr[r] - nm);
            mr[r] = nm;
            float rs = 0.f;
#pragma unroll
            for (int nt = 0; nt < 8; ++nt) {
#pragma unroll
                for (int j = 0; j < 2; ++j) {
                    float p = __expf(accs[nt][2 * r + j] - nm);
                    accs[nt][2 * r + j] = p;
                    rs += p;
                }
            }
            rs += __shfl_xor_sync(0xFFFFFFFFu, rs, 1);
            rs += __shfl_xor_sync(0xFFFFFFFFu, rs, 2);
            lr[r] = lr[r] * fac + rs;
#pragma unroll
            for (int nt = 0; nt < 8; ++nt) {
                acco[nt][2 * r + 0] *= fac;
                acco[nt][2 * r + 1] *= fac;
            }
        }

        // O += P V (split 3-MMA), V^T frags via ldmatrix.x4.trans on V[s][d]
#pragma unroll
        for (int kf2 = 0; kf2 < 4; ++kf2) {
            uint32_t pah[4], pal[4];
            float p00 = accs[2 * kf2][0],     p01 = accs[2 * kf2][1];
            float p10 = accs[2 * kf2][2],     p11 = accs[2 * kf2][3];
            float p20 = accs[2 * kf2 + 1][0], p21 = accs[2 * kf2 + 1][1];
            float p30 = accs[2 * kf2 + 1][2], p31 = accs[2 * kf2 + 1][3];
            pah[0] = packbf(p00, p01); pah[1] = packbf(p10, p11);
            pah[2] = packbf(p20, p21); pah[3] = packbf(p30, p31);
            __nv_bfloat162* hp;
            hp = (__nv_bfloat162*)&pah[0];
            pal[0] = packbf(p00 - __bfloat162float(hp->x), p01 - __bfloat162float(hp->y));
            hp = (__nv_bfloat162*)&pah[1];
            pal[1] = packbf(p10 - __bfloat162float(hp->x), p11 - __bfloat162float(hp->y));
            hp = (__nv_bfloat162*)&pah[2];
            pal[2] = packbf(p20 - __bfloat162float(hp->x), p21 - __bfloat162float(hp->y));
            hp = (__nv_bfloat162*)&pah[3];
            pal[3] = packbf(p30 - __bfloat162float(hp->x), p31 - __bfloat162float(hp->y));
#pragma unroll
            for (int ntp2 = 0; ntp2 < 4; ++ntp2) {
                uint32_t off = (uint32_t)((kf2 * 16 + vrow) * FP2 + ntp2 * 16 + vcol) * 2;
                uint32_t h0, h1, h2, h3, l0, l1, l2, l3;
                LDMX4T(h0, h1, h2, h3, vb + off);
                LDMX4T(l0, l1, l2, l3, vbl + off);
                uint32_t vh0[2] = {h0, h1}, vh1[2] = {h2, h3};
                uint32_t vl0[2] = {l0, l1}, vl1[2] = {l2, l3};
                MMA16816(acco[2*ntp2],     pah, vh0);
                MMA16816(acco[2*ntp2],     pah, vl0);
                MMA16816(acco[2*ntp2],     pal, vh0);
                MMA16816(acco[2*ntp2 + 1], pah, vh1);
                MMA16816(acco[2*ntp2 + 1], pah, vl1);
                MMA16816(acco[2*ntp2 + 1], pal, vh1);
            }
        }
        __syncthreads();
    }

    // epilogue: y = O / l, written as hi/lo bf16
#pragma unroll
    for (int r = 0; r < 2; ++r) {
        float inv = 1.0f / lr[r];
        int row = t0 + w * 16 + g + 8 * r;
#pragma unroll
        for (int nt2 = 0; nt2 < 8; ++nt2) {
            float v0 = acco[nt2][2 * r + 0] * inv;
            float v1 = acco[nt2][2 * r + 1] * inv;
            bf16 h0 = __float2bfloat16(v0);
            bf16 h1 = __float2bfloat16(v1);
            size_t idx = (size_t)(b * NTOK + row) * NE + h * DH + nt2 * 8 + 2 * tg;
            __nv_bfloat162 hp; hp.x = h0; hp.y = h1;
            *(uint32_t*)(yh + idx) = *(uint32_t*)&hp;
            *(uint32_t*)(yl + idx) = packbf(v0 - __bfloat162float(h0), v1 - __bfloat162float(h1));
        }
    }
}

// ---------------- loss: merge logsumexp partials ----------------------------------
__global__ void __launch_bounds__(256) loss_rows2(const float* __restrict__ pm,
                                                  const float* __restrict__ ps,
                                                  const float* __restrict__ logits,
                                                  const int* __restrict__ tgt,
                                                  float* __restrict__ rl) {
    int row = blockIdx.x;
    int tid = threadIdx.x;
    __shared__ float sm[256], ss[256];

    float m = -INFINITY, s = 0.f;
    for (int i = tid; i < NTP; i += 256)
        lse_merge(m, s, pm[(size_t)row * NTP + i], ps[(size_t)row * NTP + i]);
    sm[tid] = m; ss[tid] = s; __syncthreads();
    for (int o = 128; o > 0; o >>= 1) {
        if (tid < o) {
            float mm = sm[tid], sv = ss[tid];
            lse_merge(mm, sv, sm[tid + o], ss[tid + o]);
            sm[tid] = mm; ss[tid] = sv;
        }
        __syncthreads();
    }
    if (tid == 0) {
        float lt = logits[(size_t)row * NV + tgt[row]];
        rl[row] = -(lt - sm[0] - logf(ss[0]));
    }
}

__global__ void __launch_bounds__(256) loss_final(const float* __restrict__ rl,
                                                  float* __restrict__ out) {
    __shared__ float red[256];
    int tid = threadIdx.x;
    float s = 0.f;
    for (int i = tid; i < NM; i += 256) s += rl[i];
    red[tid] = s; __syncthreads();
    for (int o = 128; o > 0; o >>= 1) { if (tid < o) red[tid] += red[tid + o]; __syncthreads(); }
    if (tid == 0) out[0] = red[0] * (1.0f / NM);
}

// ---------------- host orchestration ------------------------------------------------
extern "C" void kernel_launch(void* const* d_in, const int* in_sizes, int n_in,
                              void* d_out, int out_size) {
    const int*   x0    = (const int*)  d_in[0];
    const int*   tgt   = (const int*)  d_in[1];
    const float* wte   = (const float*)d_in[2];
    const float* wpe   = (const float*)d_in[3];
    const float* ln1w  = (const float*)d_in[4];
    const float* ln1b  = (const float*)d_in[5];
    const float* Wqkv  = (const float*)d_in[6];
    const float* Wo    = (const float*)d_in[7];
    const float* ln2w  = (const float*)d_in[8];
    const float* ln2b  = (const float*)d_in[9];
    const float* Wfc   = (const float*)d_in[10];
    const float* Wproj = (const float*)d_in[11];
    const float* lnfw  = (const float*)d_in[12];
    const float* lnfb  = (const float*)d_in[13];

    float *px, *pl, *prl, *ppm, *pps;
    bf16 *pwth, *pwtl, *pwteh, *pwtel, *plnh, *plnl, *pqh, *pql, *pyh, *pyl, *pfh, *pfl;
    cudaGetSymbolAddress((void**)&px,  g_x);
    cudaGetSymbolAddress((void**)&pl,  g_logits);
    cudaGetSymbolAddress((void**)&prl, g_rl);
    cudaGetSymbolAddress((void**)&ppm, g_pm);
    cudaGetSymbolAddress((void**)&pps, g_ps);
    cudaGetSymbolAddress((void**)&pwth, g_wth);
    cudaGetSymbolAddress((void**)&pwtl, g_wtl);
    cudaGetSymbolAddress((void**)&pwteh, g_wteh);
    cudaGetSymbolAddress((void**)&pwtel, g_wtel);
    cudaGetSymbolAddress((void**)&plnh, g_lnh);
    cudaGetSymbolAddress((void**)&plnl, g_lnl);
    cudaGetSymbolAddress((void**)&pqh, g_qkvh);
    cudaGetSymbolAddress((void**)&pql, g_qkvl);
    cudaGetSymbolAddress((void**)&pyh, g_yh);
    cudaGetSymbolAddress((void**)&pyl, g_yl);
    cudaGetSymbolAddress((void**)&pfh, g_fch);
    cudaGetSymbolAddress((void**)&pfl, g_fcl);

    const int SM_WM2 = (2 * 128 * 40 * 2 + 2 * 128 * 40 * 2) * 2;  // 81920 B
    const int SM_WM4 = (2 * 128 * 40 * 2 + 2 * 64  * 40 * 2) * 2;  // 61440 B
    cudaFuncSetAttribute(gemm2<0,1,2>, cudaFuncAttributeMaxDynamicSharedMemorySize, SM_WM2);
    cudaFuncSetAttribute(gemm2<2,1,2>, cudaFuncAttributeMaxDynamicSharedMemorySize, SM_WM2);
    cudaFuncSetAttribute(gemm2<3,0,2>, cudaFuncAttributeMaxDynamicSharedMemorySize, SM_WM2);
    cudaFuncSetAttribute(gemm2<1,0,4>, cudaFuncAttributeMaxDynamicSharedMemorySize, SM_WM4);
    cudaFuncSetAttribute(flash2, cudaFuncAttributeMaxDynamicSharedMemorySize, FSMEM);

    // ---- layer 0, ordered so the 6th launch is the QKV GEMM (ncu -s 5 -c 1) ----
    size_t off0 = 0;
    embed_kernel<<<(NM * NE + 255) / 256, 256>>>(x0, wte, wpe, px);                 // 1
    tsplit2<<<dim3(N3 / 64, NE / 32), 256>>>(Wqkv, pwth, pwtl, NE, N3);             // 2
    ln_split2<<<NM / 8, 256>>>(px, ln1w, ln1b, plnh, plnl);                         // 3
    {
        int n4 = (NV * NE) / 4;
        split4<<<(n4 + 255) / 256, 256>>>(wte, pwteh, pwtel, n4);                   // 4
    }
    tsplit2<<<dim3(NE / 64, NE / 32), 256>>>(Wo, pwth + LQKV, pwtl + LQKV, NE, NE); // 5
    gemm2<0,1,2><<<dim3(N3 / 128, NM / 128), 256, SM_WM2>>>(                        // 6 (profiled)
        plnh, plnl, pwth, pwtl, nullptr, pqh, pql, nullptr,
        nullptr, nullptr, NM, N3, NE);
    flash2<<<dim3(NTOK / 64, NB * NH), 128, FSMEM>>>(pqh, pql, pyh, pyl);
    tsplit2<<<dim3(N4 / 64, NE / 32), 256>>>(Wfc, pwth + LQKV + LWO, pwtl + LQKV + LWO, NE, N4);
    tsplit2<<<dim3(NE / 64, N4 / 32), 256>>>(Wproj, pwth + LQKV + LWO + LWFC,
                                             pwtl + LQKV + LWO + LWFC, N4, NE);
    gemm2<1,0,4><<<dim3(NE / 64, NM / 128), 256, SM_WM4>>>(
        pyh, pyl, pwth + LQKV, pwtl + LQKV, px, nullptr, nullptr, px,
        nullptr, nullptr, NM, NE, NE);
    ln_split2<<<NM / 8, 256>>>(px, ln2w, ln2b, plnh, plnl);
    gemm2<2,1,2><<<dim3(N4 / 128, NM / 128), 256, SM_WM2>>>(
        plnh, plnl, pwth + LQKV + LWO, pwtl + LQKV + LWO,
        nullptr, pfh, pfl, nullptr, nullptr, nullptr, NM, N4, NE);
    gemm2<1,0,4><<<dim3(NE / 64, NM / 128), 256, SM_WM4>>>(
        pfh, pfl, pwth + LQKV + LWO + LWFC, pwtl + LQKV + LWO + LWFC,
        px, nullptr, nullptr, px, nullptr, nullptr, NM, NE, N4);
    (void)off0;

    // ---- layers 1..5 ----
    for (int l = 1; l < NL; ++l) {
        size_t off = (size_t)l * LPL;
        tsplit2<<<dim3(N3 / 64, NE / 32), 256>>>(
            Wqkv + (size_t)l * NE * N3, pwth + off, pwtl + off, NE, N3);
        tsplit2<<<dim3(NE / 64, NE / 32), 256>>>(
            Wo + (size_t)l * NE * NE, pwth + off + LQKV, pwtl + off + LQKV, NE, NE);
        tsplit2<<<dim3(N4 / 64, NE / 32), 256>>>(
            Wfc + (size_t)l * NE * N4, pwth + off + LQKV + LWO, pwtl + off + LQKV + LWO, NE, N4);
        tsplit2<<<dim3(NE / 64, N4 / 32), 256>>>(
            Wproj + (size_t)l * N4 * NE, pwth + off + LQKV + LWO + LWFC,
            pwtl + off + LQKV + LWO + LWFC, N4, NE);

        ln_split2<<<NM / 8, 256>>>(px, ln1w + (size_t)l * NE, ln1b + (size_t)l * NE, plnh, plnl);
        gemm2<0,1,2><<<dim3(N3 / 128, NM / 128), 256, SM_WM2>>>(
            plnh, plnl, pwth + off, pwtl + off, nullptr, pqh, pql, nullptr,
            nullptr, nullptr, NM, N3, NE);
        flash2<<<dim3(NTOK / 64, NB * NH), 128, FSMEM>>>(pqh, pql, pyh, pyl);
        gemm2<1,0,4><<<dim3(NE / 64, NM / 128), 256, SM_WM4>>>(
            pyh, pyl, pwth + off + LQKV, pwtl + off + LQKV, px, nullptr, nullptr, px,
            nullptr, nullptr, NM, NE, NE);
        ln_split2<<<NM / 8, 256>>>(px, ln2w + (size_t)l * NE, ln2b + (size_t)l * NE, plnh, plnl);
        gemm2<2,1,2><<<dim3(N4 / 128, NM / 128), 256, SM_WM2>>>(
            plnh, plnl, pwth + off + LQKV + LWO, pwtl + off + LQKV + LWO,
            nullptr, pfh, pfl, nullptr, nullptr, nullptr, NM, N4, NE);
        gemm2<1,0,4><<<dim3(NE / 64, NM / 128), 256, SM_WM4>>>(
            pfh, pfl, pwth + off + LQKV + LWO + LWFC, pwtl + off + LQKV + LWO + LWFC,
            px, nullptr, nullptr, px, nullptr, nullptr, NM, NE, N4);
    }

    ln_split2<<<NM / 8, 256>>>(px, lnfw, lnfb, plnh, plnl);

    const size_t logits_elems = (size_t)NM * NV;
    float* logits = ((size_t)out_size >= logits_elems) ? (float*)d_out : pl;
    gemm2<3,0,2><<<dim3(NTN, NM / 128), 256, SM_WM2>>>(
        plnh, plnl, pwteh, pwtel, logits, nullptr, nullptr, nullptr,
        ppm, pps, NM, NV, NE);

    loss_rows2<<<NM, 256>>>(ppm, pps, logits, tgt, prl);
    if ((size_t)out_size > logits_elems) {
        loss_final<<<1, 256>>>(prl, (float*)d_out + logits_elems);
    } else if (logits != (float*)d_out) {
        loss_final<<<1, 256>>>(prl, (float*)d_out);
    }
}